// round 1
// baseline (speedup 1.0000x reference)
#include <cuda_runtime.h>
#include <cstdint>

#define Bn   4
#define TEXTC 64
#define S0c  1088
#define S1c  4096
#define Sc   5184
#define Hc   1024
#define NHc  16
#define HDc  64
#define H3   3072

// ---------------- scratch (static device globals; no allocation) ----------
__device__ float g_qkv0[(size_t)Bn * S0c * H3];          // (B, S0, 3H)
__device__ float g_qkv1[(size_t)Bn * S1c * H3];          // (B, S1, 3H)
__device__ float g_sc[(size_t)Bn * NHc * S0c * S0c];     // scores/probs part0
__device__ float g_ctx[(size_t)Bn * Sc * Hc];            // concat context

// ---------------- generic tiled fp32 GEMM ---------------------------------
struct GemmP {
    const float* A; const float* Bm; float* C; const float* bias;
    int M, N, K;
    int lda, ldb, ldc;
    int Arpc;            // rows per chunk for A row mapping
    long long Achunk;    // chunk stride for A
    long long AbO, AbI, BbO, BbI, CbO, CbI;  // batch offsets: (z/NH)*O + (z%NH)*I
    int kcausal;         // 1 -> limit K loop to i0+64 (PV with zeroed upper probs)
};

// C[i,j] = sum_k A[i,k] * (BT ? B[j,k] : B[k,j])   (+ bias / scores epilogue)
// EPI: 0 = plain (+bias), 1 = scores (scale 1/8, causal mask -10000, skip upper tiles)
template <bool BT, int EPI>
__global__ __launch_bounds__(256) void gemm_k(GemmP p) {
    const int j0 = blockIdx.x * 64;
    const int i0 = blockIdx.y * 64;
    const int z  = blockIdx.z;
    if (EPI == 1 && j0 > i0 + 63) return;   // fully masked tile; never read

    const long long ao = (long long)(z / NHc) * p.AbO + (long long)(z % NHc) * p.AbI;
    const long long bo = (long long)(z / NHc) * p.BbO + (long long)(z % NHc) * p.BbI;
    const long long co = (long long)(z / NHc) * p.CbO + (long long)(z % NHc) * p.CbI;

    const float* A  = p.A + ao + (long long)(i0 / p.Arpc) * p.Achunk
                             + (long long)(i0 % p.Arpc) * p.lda;
    const float* Bm = p.Bm + bo;

    __shared__ float As[16][64];
    __shared__ float Bs[16][64];

    const int tid = threadIdx.x;
    const int ty = tid >> 4, tx = tid & 15;
    const int lr = tid >> 2, lk = (tid & 3) << 2;

    float acc[4][4] = {};

    const int kmax = p.kcausal ? ((i0 + 64 < p.K) ? (i0 + 64) : p.K) : p.K;

    for (int kb = 0; kb < kmax; kb += 16) {
        float4 va = *(const float4*)(A + (long long)lr * p.lda + kb + lk);
        As[lk + 0][lr] = va.x; As[lk + 1][lr] = va.y;
        As[lk + 2][lr] = va.z; As[lk + 3][lr] = va.w;
        if (BT) {
            float4 vb = *(const float4*)(Bm + (long long)(j0 + lr) * p.ldb + kb + lk);
            Bs[lk + 0][lr] = vb.x; Bs[lk + 1][lr] = vb.y;
            Bs[lk + 2][lr] = vb.z; Bs[lk + 3][lr] = vb.w;
        } else {
            int bk = tid >> 4, bc = (tid & 15) << 2;
            float4 vb = *(const float4*)(Bm + (long long)(kb + bk) * p.ldb + j0 + bc);
            *(float4*)&Bs[bk][bc] = vb;
        }
        __syncthreads();
#pragma unroll
        for (int kk = 0; kk < 16; kk++) {
            float4 a = *(const float4*)&As[kk][ty << 2];
            float4 b = *(const float4*)&Bs[kk][tx << 2];
            acc[0][0] += a.x * b.x; acc[0][1] += a.x * b.y;
            acc[0][2] += a.x * b.z; acc[0][3] += a.x * b.w;
            acc[1][0] += a.y * b.x; acc[1][1] += a.y * b.y;
            acc[1][2] += a.y * b.z; acc[1][3] += a.y * b.w;
            acc[2][0] += a.z * b.x; acc[2][1] += a.z * b.y;
            acc[2][2] += a.z * b.z; acc[2][3] += a.z * b.w;
            acc[3][0] += a.w * b.x; acc[3][1] += a.w * b.y;
            acc[3][2] += a.w * b.z; acc[3][3] += a.w * b.w;
        }
        __syncthreads();
    }

    float* C = p.C + co + (long long)i0 * p.ldc + j0;
    const int gj = j0 + (tx << 2);
#pragma unroll
    for (int ii = 0; ii < 4; ii++) {
        const int gi = i0 + (ty << 2) + ii;
        float4 v = make_float4(acc[ii][0], acc[ii][1], acc[ii][2], acc[ii][3]);
        if (EPI == 1) {
            v.x = (gj + 0 > gi) ? -10000.0f : v.x * 0.125f;
            v.y = (gj + 1 > gi) ? -10000.0f : v.y * 0.125f;
            v.z = (gj + 2 > gi) ? -10000.0f : v.z * 0.125f;
            v.w = (gj + 3 > gi) ? -10000.0f : v.w * 0.125f;
        } else if (p.bias) {
            v.x += p.bias[gj + 0]; v.y += p.bias[gj + 1];
            v.z += p.bias[gj + 2]; v.w += p.bias[gj + 3];
        }
        *(float4*)(C + (long long)((ty << 2) + ii) * p.ldc + (tx << 2)) = v;
    }
}

// ---------------- softmax for part-0 rows ---------------------------------
// One block per (bh, i). Softmax over j<=i; writes 0 for j>i so PV can run
// dense over truncated K tiles.
__global__ __launch_bounds__(256) void softmax0_k(float* sc) {
    const int row = blockIdx.x;
    const int bh = row / S0c;
    const int i  = row % S0c;
    float* p = sc + (long long)bh * S0c * S0c + (long long)i * S0c;
    const int len = i + 1;
    const int tid = threadIdx.x;
    __shared__ float red[256];

    float m = -1e30f;
    for (int j = tid; j < len; j += 256) m = fmaxf(m, p[j]);
    red[tid] = m; __syncthreads();
    for (int s = 128; s > 0; s >>= 1) {
        if (tid < s) red[tid] = fmaxf(red[tid], red[tid + s]);
        __syncthreads();
    }
    m = red[0]; __syncthreads();

    float sum = 0.f;
    for (int j = tid; j < len; j += 256) {
        float e = __expf(p[j] - m);
        p[j] = e;
        sum += e;
    }
    red[tid] = sum; __syncthreads();
    for (int s = 128; s > 0; s >>= 1) {
        if (tid < s) red[tid] += red[tid + s];
        __syncthreads();
    }
    const float inv = 1.0f / red[0];
    for (int j = tid; j < len; j += 256) p[j] *= inv;
    for (int j = len + tid; j < S0c; j += 256) p[j] = 0.f;
}

// ---------------- local attention (part 1): warp per position --------------
// 49 cross offsets (7x7 onto the L0 grid, downsample y/2,x/2) + 77 causal
// offsets (17x9 half-window on the L1 grid). Out-of-range neighbors follow
// the reference zero-padding: score contribution 0 (participates in softmax),
// V contribution 0.
__global__ __launch_bounds__(256) void local_attn_k(const float* __restrict__ qkv0,
                                                    const float* __restrict__ qkv1,
                                                    float* __restrict__ ctx) {
    const int gwarp = (blockIdx.x * blockDim.x + threadIdx.x) >> 5;  // 0..262143
    const int lane = threadIdx.x & 31;
    const int x  = gwarp & 63;
    const int y  = (gwarp >> 6) & 63;
    const int bh = gwarp >> 12;
    const int b = bh >> 4, h = bh & 15;

    const float* qp = qkv1 + ((long long)b * S1c + (y * 64 + x)) * H3 + h * HDc;
    float2 q = *(const float2*)(qp + lane * 2);
    q.x *= 0.125f; q.y *= 0.125f;

    const float* k0base = qkv0 + (long long)b * S0c * H3 + Hc + h * HDc;      // k of part0
    const float* k1base = qkv1 + (long long)b * S1c * H3 + Hc + h * HDc;      // k of part1
    const float* v0base = qkv0 + (long long)b * S0c * H3 + 2 * Hc + h * HDc;  // v of part0
    const float* v1base = qkv1 + (long long)b * S1c * H3 + 2 * Hc + h * HDc;  // v of part1

    float sreg[4] = {-1e30f, -1e30f, -1e30f, -1e30f};

    // cross offsets: o in [0,49)
#pragma unroll
    for (int o = 0; o < 49; o++) {
        const int dy = o / 7 - 3, dx = o % 7 - 3;
        const int yy = (y >> 1) + dy, xx = (x >> 1) + dx;
        float s = 0.f;
        if ((unsigned)yy < 32u && (unsigned)xx < 32u) {
            float2 k = *(const float2*)(k0base + (long long)(TEXTC + yy * 32 + xx) * H3 + lane * 2);
            float t = q.x * k.x + q.y * k.y;
            t += __shfl_xor_sync(0xffffffffu, t, 16);
            t += __shfl_xor_sync(0xffffffffu, t, 8);
            t += __shfl_xor_sync(0xffffffffu, t, 4);
            t += __shfl_xor_sync(0xffffffffu, t, 2);
            t += __shfl_xor_sync(0xffffffffu, t, 1);
            s = t;
        }
        if (lane == (o & 31)) sreg[o >> 5] = s;
    }
    // causal offsets: o in [49,126)
#pragma unroll
    for (int o = 49; o < 126; o++) {
        const int oc = o - 49;
        const int dy = oc / 9 - 8, dx = oc % 9 - 4;
        const int ny = y + dy, nx = x + dx;
        float s = 0.f;
        if ((unsigned)ny < 64u && (unsigned)nx < 64u) {
            float2 k = *(const float2*)(k1base + (long long)(ny * 64 + nx) * H3 + lane * 2);
            float t = q.x * k.x + q.y * k.y;
            t += __shfl_xor_sync(0xffffffffu, t, 16);
            t += __shfl_xor_sync(0xffffffffu, t, 8);
            t += __shfl_xor_sync(0xffffffffu, t, 4);
            t += __shfl_xor_sync(0xffffffffu, t, 2);
            t += __shfl_xor_sync(0xffffffffu, t, 1);
            s = t;
        }
        if (lane == (o & 31)) sreg[o >> 5] = s;
    }

    // warp softmax over 126 lane-distributed scores
    float m = fmaxf(fmaxf(sreg[0], sreg[1]), fmaxf(sreg[2], sreg[3]));
    m = fmaxf(m, __shfl_xor_sync(0xffffffffu, m, 16));
    m = fmaxf(m, __shfl_xor_sync(0xffffffffu, m, 8));
    m = fmaxf(m, __shfl_xor_sync(0xffffffffu, m, 4));
    m = fmaxf(m, __shfl_xor_sync(0xffffffffu, m, 2));
    m = fmaxf(m, __shfl_xor_sync(0xffffffffu, m, 1));
    float e0 = __expf(sreg[0] - m), e1 = __expf(sreg[1] - m);
    float e2 = __expf(sreg[2] - m), e3 = __expf(sreg[3] - m);
    float sum = e0 + e1 + e2 + e3;
    sum += __shfl_xor_sync(0xffffffffu, sum, 16);
    sum += __shfl_xor_sync(0xffffffffu, sum, 8);
    sum += __shfl_xor_sync(0xffffffffu, sum, 4);
    sum += __shfl_xor_sync(0xffffffffu, sum, 2);
    sum += __shfl_xor_sync(0xffffffffu, sum, 1);
    const float inv = 1.0f / sum;
    sreg[0] = e0 * inv; sreg[1] = e1 * inv; sreg[2] = e2 * inv; sreg[3] = e3 * inv;

    // weighted sum of V
    float2 out = make_float2(0.f, 0.f);
#pragma unroll
    for (int o = 0; o < 49; o++) {
        const int dy = o / 7 - 3, dx = o % 7 - 3;
        const int yy = (y >> 1) + dy, xx = (x >> 1) + dx;
        const float pw = __shfl_sync(0xffffffffu, sreg[o >> 5], o & 31);
        if ((unsigned)yy < 32u && (unsigned)xx < 32u) {
            float2 v = *(const float2*)(v0base + (long long)(TEXTC + yy * 32 + xx) * H3 + lane * 2);
            out.x += pw * v.x; out.y += pw * v.y;
        }
    }
#pragma unroll
    for (int o = 49; o < 126; o++) {
        const int oc = o - 49;
        const int dy = oc / 9 - 8, dx = oc % 9 - 4;
        const int ny = y + dy, nx = x + dx;
        const float pw = __shfl_sync(0xffffffffu, sreg[o >> 5], o & 31);
        if ((unsigned)ny < 64u && (unsigned)nx < 64u) {
            float2 v = *(const float2*)(v1base + (long long)(ny * 64 + nx) * H3 + lane * 2);
            out.x += pw * v.x; out.y += pw * v.y;
        }
    }

    float* cp = ctx + ((long long)b * Sc + S0c + y * 64 + x) * Hc + h * HDc;
    *(float2*)(cp + lane * 2) = out;
}

// ---------------- host launch ---------------------------------------------
extern "C" void kernel_launch(void* const* d_in, const int* in_sizes, int n_in,
                              void* d_out, int out_size) {
    const float* hidden  = (const float*)d_in[0];
    // d_in[1] = mask (tril) — causal handled analytically
    const float* W_qkv   = (const float*)d_in[2];
    const float* b_qkv   = (const float*)d_in[3];
    const float* W_qkvp  = (const float*)d_in[4];
    const float* b_qkvp  = (const float*)d_in[5];
    const float* W_dense = (const float*)d_in[6];
    const float* b_dense = (const float*)d_in[7];
    float* out = (float*)d_out;

    float *qkv0, *qkv1, *sc, *ctx;
    cudaGetSymbolAddress((void**)&qkv0, g_qkv0);
    cudaGetSymbolAddress((void**)&qkv1, g_qkv1);
    cudaGetSymbolAddress((void**)&sc, g_sc);
    cudaGetSymbolAddress((void**)&ctx, g_ctx);

    const int BIG = 1 << 30;

    // 1) QKV for part 0: (B*S0, 1024) @ (1024, 3072) + bias
    {
        GemmP p = {};
        p.A = hidden; p.Bm = W_qkv; p.C = qkv0; p.bias = b_qkv;
        p.M = Bn * S0c; p.N = H3; p.K = Hc;
        p.lda = Hc; p.ldb = H3; p.ldc = H3;
        p.Arpc = S0c; p.Achunk = (long long)Sc * Hc;
        gemm_k<false, 0><<<dim3(H3 / 64, Bn * S0c / 64, 1), 256>>>(p);
    }
    // 2) QKV for part 1
    {
        GemmP p = {};
        p.A = hidden + (long long)S0c * Hc; p.Bm = W_qkvp; p.C = qkv1; p.bias = b_qkvp;
        p.M = Bn * S1c; p.N = H3; p.K = Hc;
        p.lda = Hc; p.ldb = H3; p.ldc = H3;
        p.Arpc = S1c; p.Achunk = (long long)Sc * Hc;
        gemm_k<false, 0><<<dim3(H3 / 64, Bn * S1c / 64, 1), 256>>>(p);
    }
    // 3) scores0 = (Q0/8) @ K0^T with causal mask, batched over 64 (b,h)
    {
        GemmP p = {};
        p.A = qkv0; p.Bm = qkv0 + Hc; p.C = sc; p.bias = nullptr;
        p.M = S0c; p.N = S0c; p.K = HDc;
        p.lda = H3; p.ldb = H3; p.ldc = S0c;
        p.Arpc = BIG; p.Achunk = 0;
        p.AbO = (long long)S0c * H3; p.AbI = HDc;
        p.BbO = (long long)S0c * H3; p.BbI = HDc;
        p.CbO = (long long)NHc * S0c * S0c; p.CbI = (long long)S0c * S0c;
        gemm_k<true, 1><<<dim3(S0c / 64, S0c / 64, Bn * NHc), 256>>>(p);
    }
    // 4) softmax over rows (in place; zeros above diagonal)
    softmax0_k<<<Bn * NHc * S0c, 256>>>(sc);
    // 5) context0 = P @ V0 (K truncated causally), write into ctx (B,S,H)
    {
        GemmP p = {};
        p.A = sc; p.Bm = qkv0 + 2 * Hc; p.C = ctx; p.bias = nullptr;
        p.M = S0c; p.N = HDc; p.K = S0c;
        p.lda = S0c; p.ldb = H3; p.ldc = Hc;
        p.Arpc = BIG; p.Achunk = 0;
        p.AbO = (long long)NHc * S0c * S0c; p.AbI = (long long)S0c * S0c;
        p.BbO = (long long)S0c * H3; p.BbI = HDc;
        p.CbO = (long long)Sc * Hc; p.CbI = HDc;
        p.kcausal = 1;
        gemm_k<false, 0><<<dim3(1, S0c / 64, Bn * NHc), 256>>>(p);
    }
    // 6) local attention for part 1 (writes ctx rows S0..S-1)
    local_attn_k<<<(Bn * NHc * 64 * 64 * 32) / 256, 256>>>(qkv0, qkv1, ctx);
    // 7) out = ctx @ W_dense + b_dense
    {
        GemmP p = {};
        p.A = ctx; p.Bm = W_dense; p.C = out; p.bias = b_dense;
        p.M = Bn * Sc; p.N = Hc; p.K = Hc;
        p.lda = Hc; p.ldb = Hc; p.ldc = Hc;
        p.Arpc = BIG; p.Achunk = 0;
        gemm_k<false, 0><<<dim3(Hc / 64, Bn * Sc / 64, 1), 256>>>(p);
    }
}

// round 2
// speedup vs baseline: 1.0917x; 1.0917x over previous
#include <cuda_runtime.h>
#include <cstdint>

#define Bn   4
#define TEXTC 64
#define S0c  1088
#define S1c  4096
#define Sc   5184
#define Hc   1024
#define NHc  16
#define HDc  64
#define H3   3072

// ---------------- scratch (static device globals; no allocation) ----------
__device__ float g_qkv0[(size_t)Bn * S0c * H3];          // (B, S0, 3H)
__device__ float g_qkv1[(size_t)Bn * S1c * H3];          // (B, S1, 3H)
__device__ float g_sc[(size_t)Bn * NHc * S0c * S0c];     // scores/probs part0
__device__ float g_ctx[(size_t)Bn * Sc * Hc];            // concat context

// ---------------- GEMM parameter block -------------------------------------
struct GemmP {
    const float* A; const float* Bm; float* C; const float* bias;
    int K;
    int lda, ldb, ldc;
    int Arpc;            // rows per chunk for A row mapping (batch folding)
    long long Achunk;    // chunk stride for A
    long long AbO, AbI, BbO, BbI, CbO, CbI;  // z offsets: (z/NH)*O + (z%NH)*I
    int kcausal;         // 1 -> limit K loop to i0+BM (PV with zeroed upper probs)
};

// C[i,j] = sum_k A[i,k] * (BT ? B[j,k] : B[k,j])
// EPI: 0 = plain (+bias), 1 = scores (scale 1/8, causal -10000, skip upper tiles)
// Requirements: threads = (BM/TM)*(BN/TN) = 2*BM = 2*BN; BK=8; M,N multiples of BM,BN.
template <int BM, int BN, int TM, int TN, bool BT, int EPI>
__global__ __launch_bounds__((BM / TM) * (BN / TN)) void gemm_k(GemmP p) {
    constexpr int BK = 8;
    const int tid = threadIdx.x;
    const int j0 = blockIdx.x * BN;
    const int i0 = blockIdx.y * BM;
    const int z  = blockIdx.z;
    if (EPI == 1 && j0 > i0 + BM - 1) return;   // fully masked tile

    const long long ao = (long long)(z / NHc) * p.AbO + (long long)(z % NHc) * p.AbI;
    const long long bo = (long long)(z / NHc) * p.BbO + (long long)(z % NHc) * p.BbI;
    const long long co = (long long)(z / NHc) * p.CbO + (long long)(z % NHc) * p.CbI;

    __shared__ float As[2][BK][BM];
    __shared__ float Bs[2][BK][BN];

    // A loading: each thread owns one row, half of BK (float4)
    const int ar = tid >> 1;
    const int ak = (tid & 1) * 4;
    const int gr = i0 + ar;
    const float* Arow = p.A + ao + (long long)(gr / p.Arpc) * p.Achunk
                               + (long long)(gr % p.Arpc) * p.lda + ak;
    // B loading
    const float* Bbase = p.Bm + bo;
    const int br = BT ? (tid >> 1) : (tid / (BN / 4));
    const int bc = BT ? (tid & 1) * 4 : (tid % (BN / 4)) * 4;

    // compute mapping
    const int ry = (tid / (BN / TN)) * TM;
    const int rx = (tid % (BN / TN)) * TN;

    float acc[TM][TN] = {};

    const int kmax = p.kcausal ? ((i0 + BM < p.K) ? (i0 + BM) : p.K) : p.K;

    // prologue: load tile 0
    float4 va = *(const float4*)(Arow + 0);
    float4 vb;
    if (BT) vb = *(const float4*)(Bbase + (long long)(j0 + br) * p.ldb + bc);
    else    vb = *(const float4*)(Bbase + (long long)br * p.ldb + j0 + bc);
    As[0][ak + 0][ar] = va.x; As[0][ak + 1][ar] = va.y;
    As[0][ak + 2][ar] = va.z; As[0][ak + 3][ar] = va.w;
    if (BT) {
        Bs[0][bc + 0][br] = vb.x; Bs[0][bc + 1][br] = vb.y;
        Bs[0][bc + 2][br] = vb.z; Bs[0][bc + 3][br] = vb.w;
    } else {
        *(float4*)&Bs[0][br][bc] = vb;
    }
    __syncthreads();

    int buf = 0;
    for (int kb = 0; kb < kmax; kb += BK) {
        const int nkb = kb + BK;
        if (nkb < kmax) {
            va = *(const float4*)(Arow + nkb);
            if (BT) vb = *(const float4*)(Bbase + (long long)(j0 + br) * p.ldb + nkb + bc);
            else    vb = *(const float4*)(Bbase + (long long)(nkb + br) * p.ldb + j0 + bc);
        }
#pragma unroll
        for (int kk = 0; kk < BK; kk++) {
            float a[TM], b[TN];
#pragma unroll
            for (int i = 0; i < TM; i += 4)
                *(float4*)&a[i] = *(const float4*)&As[buf][kk][ry + i];
#pragma unroll
            for (int j = 0; j < TN; j += 4)
                *(float4*)&b[j] = *(const float4*)&Bs[buf][kk][rx + j];
#pragma unroll
            for (int i = 0; i < TM; i++)
#pragma unroll
                for (int j = 0; j < TN; j++)
                    acc[i][j] += a[i] * b[j];
        }
        if (nkb < kmax) {
            const int nb = buf ^ 1;
            As[nb][ak + 0][ar] = va.x; As[nb][ak + 1][ar] = va.y;
            As[nb][ak + 2][ar] = va.z; As[nb][ak + 3][ar] = va.w;
            if (BT) {
                Bs[nb][bc + 0][br] = vb.x; Bs[nb][bc + 1][br] = vb.y;
                Bs[nb][bc + 2][br] = vb.z; Bs[nb][bc + 3][br] = vb.w;
            } else {
                *(float4*)&Bs[nb][br][bc] = vb;
            }
            __syncthreads();
            buf = nb;
        }
    }

    float* C = p.C + co + (long long)i0 * p.ldc + j0;
#pragma unroll
    for (int ii = 0; ii < TM; ii++) {
        const int gi = i0 + ry + ii;
#pragma unroll
        for (int jj = 0; jj < TN; jj += 4) {
            float4 v = make_float4(acc[ii][jj], acc[ii][jj + 1],
                                   acc[ii][jj + 2], acc[ii][jj + 3]);
            const int gj = j0 + rx + jj;
            if (EPI == 1) {
                v.x = (gj + 0 > gi) ? -10000.0f : v.x * 0.125f;
                v.y = (gj + 1 > gi) ? -10000.0f : v.y * 0.125f;
                v.z = (gj + 2 > gi) ? -10000.0f : v.z * 0.125f;
                v.w = (gj + 3 > gi) ? -10000.0f : v.w * 0.125f;
            } else if (p.bias) {
                v.x += p.bias[gj + 0]; v.y += p.bias[gj + 1];
                v.z += p.bias[gj + 2]; v.w += p.bias[gj + 3];
            }
            *(float4*)(C + (long long)(ry + ii) * p.ldc + rx + jj) = v;
        }
    }
}

// ---------------- softmax for part-0 rows ---------------------------------
__global__ __launch_bounds__(256) void softmax0_k(float* sc) {
    const int row = blockIdx.x;
    const int bh = row / S0c;
    const int i  = row % S0c;
    float* p = sc + (long long)bh * S0c * S0c + (long long)i * S0c;
    const int len = i + 1;
    const int tid = threadIdx.x;
    __shared__ float red[256];

    float m = -1e30f;
    for (int j = tid; j < len; j += 256) m = fmaxf(m, p[j]);
    red[tid] = m; __syncthreads();
    for (int s = 128; s > 0; s >>= 1) {
        if (tid < s) red[tid] = fmaxf(red[tid], red[tid + s]);
        __syncthreads();
    }
    m = red[0]; __syncthreads();

    float sum = 0.f;
    for (int j = tid; j < len; j += 256) {
        float e = __expf(p[j] - m);
        p[j] = e;
        sum += e;
    }
    red[tid] = sum; __syncthreads();
    for (int s = 128; s > 0; s >>= 1) {
        if (tid < s) red[tid] += red[tid + s];
        __syncthreads();
    }
    const float inv = 1.0f / red[0];
    for (int j = tid; j < len; j += 256) p[j] *= inv;
    for (int j = len + tid; j < S0c; j += 256) p[j] = 0.f;
}

// ---------------- local attention (part 1): warp per position --------------
__global__ __launch_bounds__(256) void local_attn_k(const float* __restrict__ qkv0,
                                                    const float* __restrict__ qkv1,
                                                    float* __restrict__ ctx) {
    const int gwarp = (blockIdx.x * blockDim.x + threadIdx.x) >> 5;
    const int lane = threadIdx.x & 31;
    const int x  = gwarp & 63;
    const int y  = (gwarp >> 6) & 63;
    const int bh = gwarp >> 12;
    const int b = bh >> 4, h = bh & 15;

    const float* qp = qkv1 + ((long long)b * S1c + (y * 64 + x)) * H3 + h * HDc;
    float2 q = *(const float2*)(qp + lane * 2);
    q.x *= 0.125f; q.y *= 0.125f;

    const float* k0base = qkv0 + (long long)b * S0c * H3 + Hc + h * HDc;
    const float* k1base = qkv1 + (long long)b * S1c * H3 + Hc + h * HDc;
    const float* v0base = qkv0 + (long long)b * S0c * H3 + 2 * Hc + h * HDc;
    const float* v1base = qkv1 + (long long)b * S1c * H3 + 2 * Hc + h * HDc;

    float sreg[4] = {-1e30f, -1e30f, -1e30f, -1e30f};

#pragma unroll
    for (int o = 0; o < 49; o++) {
        const int dy = o / 7 - 3, dx = o % 7 - 3;
        const int yy = (y >> 1) + dy, xx = (x >> 1) + dx;
        float s = 0.f;
        if ((unsigned)yy < 32u && (unsigned)xx < 32u) {
            float2 k = *(const float2*)(k0base + (long long)(TEXTC + yy * 32 + xx) * H3 + lane * 2);
            float t = q.x * k.x + q.y * k.y;
            t += __shfl_xor_sync(0xffffffffu, t, 16);
            t += __shfl_xor_sync(0xffffffffu, t, 8);
            t += __shfl_xor_sync(0xffffffffu, t, 4);
            t += __shfl_xor_sync(0xffffffffu, t, 2);
            t += __shfl_xor_sync(0xffffffffu, t, 1);
            s = t;
        }
        if (lane == (o & 31)) sreg[o >> 5] = s;
    }
#pragma unroll
    for (int o = 49; o < 126; o++) {
        const int oc = o - 49;
        const int dy = oc / 9 - 8, dx = oc % 9 - 4;
        const int ny = y + dy, nx = x + dx;
        float s = 0.f;
        if ((unsigned)ny < 64u && (unsigned)nx < 64u) {
            float2 k = *(const float2*)(k1base + (long long)(ny * 64 + nx) * H3 + lane * 2);
            float t = q.x * k.x + q.y * k.y;
            t += __shfl_xor_sync(0xffffffffu, t, 16);
            t += __shfl_xor_sync(0xffffffffu, t, 8);
            t += __shfl_xor_sync(0xffffffffu, t, 4);
            t += __shfl_xor_sync(0xffffffffu, t, 2);
            t += __shfl_xor_sync(0xffffffffu, t, 1);
            s = t;
        }
        if (lane == (o & 31)) sreg[o >> 5] = s;
    }

    float m = fmaxf(fmaxf(sreg[0], sreg[1]), fmaxf(sreg[2], sreg[3]));
    m = fmaxf(m, __shfl_xor_sync(0xffffffffu, m, 16));
    m = fmaxf(m, __shfl_xor_sync(0xffffffffu, m, 8));
    m = fmaxf(m, __shfl_xor_sync(0xffffffffu, m, 4));
    m = fmaxf(m, __shfl_xor_sync(0xffffffffu, m, 2));
    m = fmaxf(m, __shfl_xor_sync(0xffffffffu, m, 1));
    float e0 = __expf(sreg[0] - m), e1 = __expf(sreg[1] - m);
    float e2 = __expf(sreg[2] - m), e3 = __expf(sreg[3] - m);
    float sum = e0 + e1 + e2 + e3;
    sum += __shfl_xor_sync(0xffffffffu, sum, 16);
    sum += __shfl_xor_sync(0xffffffffu, sum, 8);
    sum += __shfl_xor_sync(0xffffffffu, sum, 4);
    sum += __shfl_xor_sync(0xffffffffu, sum, 2);
    sum += __shfl_xor_sync(0xffffffffu, sum, 1);
    const float inv = 1.0f / sum;
    sreg[0] = e0 * inv; sreg[1] = e1 * inv; sreg[2] = e2 * inv; sreg[3] = e3 * inv;

    float2 out = make_float2(0.f, 0.f);
#pragma unroll
    for (int o = 0; o < 49; o++) {
        const int dy = o / 7 - 3, dx = o % 7 - 3;
        const int yy = (y >> 1) + dy, xx = (x >> 1) + dx;
        const float pw = __shfl_sync(0xffffffffu, sreg[o >> 5], o & 31);
        if ((unsigned)yy < 32u && (unsigned)xx < 32u) {
            float2 v = *(const float2*)(v0base + (long long)(TEXTC + yy * 32 + xx) * H3 + lane * 2);
            out.x += pw * v.x; out.y += pw * v.y;
        }
    }
#pragma unroll
    for (int o = 49; o < 126; o++) {
        const int oc = o - 49;
        const int dy = oc / 9 - 8, dx = oc % 9 - 4;
        const int ny = y + dy, nx = x + dx;
        const float pw = __shfl_sync(0xffffffffu, sreg[o >> 5], o & 31);
        if ((unsigned)ny < 64u && (unsigned)nx < 64u) {
            float2 v = *(const float2*)(v1base + (long long)(ny * 64 + nx) * H3 + lane * 2);
            out.x += pw * v.x; out.y += pw * v.y;
        }
    }

    float* cp = ctx + ((long long)b * Sc + S0c + y * 64 + x) * Hc + h * HDc;
    *(float2*)(cp + lane * 2) = out;
}

// ---------------- host launch ---------------------------------------------
extern "C" void kernel_launch(void* const* d_in, const int* in_sizes, int n_in,
                              void* d_out, int out_size) {
    const float* hidden  = (const float*)d_in[0];
    const float* W_qkv   = (const float*)d_in[2];
    const float* b_qkv   = (const float*)d_in[3];
    const float* W_qkvp  = (const float*)d_in[4];
    const float* b_qkvp  = (const float*)d_in[5];
    const float* W_dense = (const float*)d_in[6];
    const float* b_dense = (const float*)d_in[7];
    float* out = (float*)d_out;

    float *qkv0, *qkv1, *sc, *ctx;
    cudaGetSymbolAddress((void**)&qkv0, g_qkv0);
    cudaGetSymbolAddress((void**)&qkv1, g_qkv1);
    cudaGetSymbolAddress((void**)&sc, g_sc);
    cudaGetSymbolAddress((void**)&ctx, g_ctx);

    const int BIG = 1 << 30;

    // 1) QKV for part 0: (B*S0, 1024) @ (1024, 3072) + bias
    {
        GemmP p = {};
        p.A = hidden; p.Bm = W_qkv; p.C = qkv0; p.bias = b_qkv;
        p.K = Hc; p.lda = Hc; p.ldb = H3; p.ldc = H3;
        p.Arpc = S0c; p.Achunk = (long long)Sc * Hc;
        gemm_k<128, 128, 8, 8, false, 0><<<dim3(H3 / 128, Bn * S0c / 128, 1), 256>>>(p);
    }
    // 2) QKV for part 1
    {
        GemmP p = {};
        p.A = hidden + (long long)S0c * Hc; p.Bm = W_qkvp; p.C = qkv1; p.bias = b_qkvp;
        p.K = Hc; p.lda = Hc; p.ldb = H3; p.ldc = H3;
        p.Arpc = S1c; p.Achunk = (long long)Sc * Hc;
        gemm_k<128, 128, 8, 8, false, 0><<<dim3(H3 / 128, Bn * S1c / 128, 1), 256>>>(p);
    }
    // 3) scores0 = (Q0/8) @ K0^T with causal mask, batched over 64 (b,h)
    {
        GemmP p = {};
        p.A = qkv0; p.Bm = qkv0 + Hc; p.C = sc; p.bias = nullptr;
        p.K = HDc; p.lda = H3; p.ldb = H3; p.ldc = S0c;
        p.Arpc = BIG; p.Achunk = 0;
        p.AbO = (long long)S0c * H3; p.AbI = HDc;
        p.BbO = (long long)S0c * H3; p.BbI = HDc;
        p.CbO = (long long)NHc * S0c * S0c; p.CbI = (long long)S0c * S0c;
        gemm_k<64, 64, 8, 4, true, 1><<<dim3(S0c / 64, S0c / 64, Bn * NHc), 128>>>(p);
    }
    // 4) softmax over rows (in place; zeros above diagonal)
    softmax0_k<<<Bn * NHc * S0c, 256>>>(sc);
    // 5) context0 = P @ V0 (K truncated causally), write into ctx (B,S,H)
    {
        GemmP p = {};
        p.A = sc; p.Bm = qkv0 + 2 * Hc; p.C = ctx; p.bias = nullptr;
        p.K = S0c; p.lda = S0c; p.ldb = H3; p.ldc = Hc;
        p.Arpc = BIG; p.Achunk = 0;
        p.AbO = (long long)NHc * S0c * S0c; p.AbI = (long long)S0c * S0c;
        p.BbO = (long long)S0c * H3; p.BbI = HDc;
        p.CbO = (long long)Sc * Hc; p.CbI = HDc;
        p.kcausal = 1;
        gemm_k<64, 64, 8, 4, false, 0><<<dim3(1, S0c / 64, Bn * NHc), 128>>>(p);
    }
    // 6) local attention for part 1 (writes ctx rows S0..S-1)
    local_attn_k<<<(Bn * NHc * 64 * 64 * 32) / 256, 256>>>(qkv0, qkv1, ctx);
    // 7) out = ctx @ W_dense + b_dense
    {
        GemmP p = {};
        p.A = ctx; p.Bm = W_dense; p.C = out; p.bias = b_dense;
        p.K = Hc; p.lda = Hc; p.ldb = Hc; p.ldc = Hc;
        p.Arpc = BIG; p.Achunk = 0;
        gemm_k<128, 128, 8, 8, false, 0><<<dim3(Hc / 128, Bn * Sc / 128, 1), 256>>>(p);
    }
}

// round 3
// speedup vs baseline: 1.2936x; 1.1849x over previous
#include <cuda_runtime.h>
#include <cstdint>

#define Bn   4
#define TEXTC 64
#define S0c  1088
#define S1c  4096
#define Sc   5184
#define Hc   1024
#define NHc  16
#define HDc  64
#define H3   3072

// ---------------- scratch (static device globals; no allocation) ----------
__device__ float g_qkv0[(size_t)Bn * S0c * H3];          // (B, S0, 3H)
__device__ float g_qkv1[(size_t)Bn * S1c * H3];          // (B, S1, 3H)
__device__ float g_sc[(size_t)Bn * NHc * S0c * S0c];     // scores/probs part0
__device__ float g_ctx[(size_t)Bn * Sc * Hc];            // concat context

// ---------------- GEMM parameter block -------------------------------------
struct GemmP {
    const float* A; const float* Bm; float* C; const float* bias;
    int K;
    int lda, ldb, ldc;
    int Arpc;            // rows per chunk for A row mapping (batch folding)
    long long Achunk;    // chunk stride for A
    long long AbO, AbI, BbO, BbI, CbO, CbI;  // z offsets: (z/NH)*O + (z%NH)*I
    int kcausal;
};

// =================== tf32 tensor-core GEMM (plain, +bias) ==================
// C = A @ B (+bias). A row-major [M,K] (with per-row batch-chunk folding),
// B row-major [K,N], C row-major. M % 128 == 0, N % 128 == 0, K % 16 == 0.
// 256 threads, 8 warps as 2(m) x 4(n), warp tile 64x32, mma m16n8k8.
__device__ __forceinline__ uint32_t f2tf32(float x) {
    uint32_t r;
    asm("cvt.rna.tf32.f32 %0, %1;" : "=r"(r) : "f"(x));
    return r;
}

#define SA 136   // smem row stride (floats); (SA%32)*4 spread avoids conflicts

__global__ __launch_bounds__(256) void gemm_tf32_k(GemmP p) {
    const int tid = threadIdx.x;
    const int i0 = blockIdx.y * 128;
    const int j0 = blockIdx.x * 128;

    __shared__ uint32_t As[2][16][SA];
    __shared__ uint32_t Bs[2][16][SA];

    // --- loader mapping ---
    // A: thread owns row am, k-range [ak, ak+8) as two float4
    const int am = tid & 127;
    const int ak = (tid >> 7) * 8;
    const int gr = i0 + am;
    const float* Arow = p.A + (long long)(gr / p.Arpc) * p.Achunk
                            + (long long)(gr % p.Arpc) * p.lda + ak;
    // B: thread owns k rows bk and bk+8, 4 columns at bn
    const int bn = (tid & 31) * 4;
    const int bk = tid >> 5;
    const float* Brow = p.Bm + (long long)bk * p.ldb + j0 + bn;

    // --- compute mapping ---
    const int lane = tid & 31;
    const int wid = tid >> 5;
    const int wm = (wid >> 2) * 64;   // warp m offset in tile
    const int wn = (wid & 3) * 32;    // warp n offset in tile
    const int lg = lane >> 2;         // group id 0..7
    const int lk = lane & 3;          // k id 0..3

    float acc[4][4][4] = {};

    // prologue: load tile 0
    float4 a0 = *(const float4*)(Arow + 0);
    float4 a1 = *(const float4*)(Arow + 4);
    float4 b0 = *(const float4*)(Brow);
    float4 b1 = *(const float4*)(Brow + 8 * p.ldb);
    {
        As[0][ak + 0][am] = f2tf32(a0.x); As[0][ak + 1][am] = f2tf32(a0.y);
        As[0][ak + 2][am] = f2tf32(a0.z); As[0][ak + 3][am] = f2tf32(a0.w);
        As[0][ak + 4][am] = f2tf32(a1.x); As[0][ak + 5][am] = f2tf32(a1.y);
        As[0][ak + 6][am] = f2tf32(a1.z); As[0][ak + 7][am] = f2tf32(a1.w);
        uint4 u0 = make_uint4(f2tf32(b0.x), f2tf32(b0.y), f2tf32(b0.z), f2tf32(b0.w));
        uint4 u1 = make_uint4(f2tf32(b1.x), f2tf32(b1.y), f2tf32(b1.z), f2tf32(b1.w));
        *(uint4*)&Bs[0][bk][bn]     = u0;
        *(uint4*)&Bs[0][bk + 8][bn] = u1;
    }
    __syncthreads();

    int buf = 0;
    for (int kb = 0; kb < p.K; kb += 16) {
        const int nkb = kb + 16;
        if (nkb < p.K) {
            a0 = *(const float4*)(Arow + nkb);
            a1 = *(const float4*)(Arow + nkb + 4);
            b0 = *(const float4*)(Brow + (long long)nkb * p.ldb);
            b1 = *(const float4*)(Brow + (long long)(nkb + 8) * p.ldb);
        }
#pragma unroll
        for (int ks = 0; ks < 16; ks += 8) {
            uint32_t af[4][4], bf[4][2];
#pragma unroll
            for (int mf = 0; mf < 4; mf++) {
                const int r0 = wm + mf * 16 + lg;
                af[mf][0] = As[buf][ks + lk][r0];
                af[mf][1] = As[buf][ks + lk][r0 + 8];
                af[mf][2] = As[buf][ks + 4 + lk][r0];
                af[mf][3] = As[buf][ks + 4 + lk][r0 + 8];
            }
#pragma unroll
            for (int nf = 0; nf < 4; nf++) {
                const int c0 = wn + nf * 8 + lg;
                bf[nf][0] = Bs[buf][ks + lk][c0];
                bf[nf][1] = Bs[buf][ks + 4 + lk][c0];
            }
#pragma unroll
            for (int mf = 0; mf < 4; mf++)
#pragma unroll
                for (int nf = 0; nf < 4; nf++) {
                    float* d = acc[mf][nf];
                    asm volatile(
                        "mma.sync.aligned.m16n8k8.row.col.f32.tf32.tf32.f32 "
                        "{%0,%1,%2,%3}, {%4,%5,%6,%7}, {%8,%9}, {%0,%1,%2,%3};\n"
                        : "+f"(d[0]), "+f"(d[1]), "+f"(d[2]), "+f"(d[3])
                        : "r"(af[mf][0]), "r"(af[mf][1]), "r"(af[mf][2]), "r"(af[mf][3]),
                          "r"(bf[nf][0]), "r"(bf[nf][1]));
                }
        }
        if (nkb < p.K) {
            const int nb = buf ^ 1;
            As[nb][ak + 0][am] = f2tf32(a0.x); As[nb][ak + 1][am] = f2tf32(a0.y);
            As[nb][ak + 2][am] = f2tf32(a0.z); As[nb][ak + 3][am] = f2tf32(a0.w);
            As[nb][ak + 4][am] = f2tf32(a1.x); As[nb][ak + 5][am] = f2tf32(a1.y);
            As[nb][ak + 6][am] = f2tf32(a1.z); As[nb][ak + 7][am] = f2tf32(a1.w);
            uint4 u0 = make_uint4(f2tf32(b0.x), f2tf32(b0.y), f2tf32(b0.z), f2tf32(b0.w));
            uint4 u1 = make_uint4(f2tf32(b1.x), f2tf32(b1.y), f2tf32(b1.z), f2tf32(b1.w));
            *(uint4*)&Bs[nb][bk][bn]     = u0;
            *(uint4*)&Bs[nb][bk + 8][bn] = u1;
            __syncthreads();
            buf = nb;
        }
    }

    // epilogue
    float* C = p.C + (long long)i0 * p.ldc + j0;
#pragma unroll
    for (int mf = 0; mf < 4; mf++) {
#pragma unroll
        for (int nf = 0; nf < 4; nf++) {
            const int r = wm + mf * 16 + lg;
            const int c = wn + nf * 8 + (lk << 1);
            float bx = 0.f, by = 0.f;
            if (p.bias) { bx = p.bias[j0 + c]; by = p.bias[j0 + c + 1]; }
            float2 v0 = make_float2(acc[mf][nf][0] + bx, acc[mf][nf][1] + by);
            float2 v1 = make_float2(acc[mf][nf][2] + bx, acc[mf][nf][3] + by);
            *(float2*)(C + (long long)r * p.ldc + c)       = v0;
            *(float2*)(C + (long long)(r + 8) * p.ldc + c) = v1;
        }
    }
}

// =================== fp32 SGEMM (scores / PV) ==============================
template <int BM, int BN, int TM, int TN, bool BT, int EPI>
__global__ __launch_bounds__((BM / TM) * (BN / TN)) void gemm_k(GemmP p) {
    constexpr int BK = 8;
    const int tid = threadIdx.x;
    const int j0 = blockIdx.x * BN;
    const int i0 = blockIdx.y * BM;
    const int z  = blockIdx.z;
    if (EPI == 1 && j0 > i0 + BM - 1) return;

    const long long ao = (long long)(z / NHc) * p.AbO + (long long)(z % NHc) * p.AbI;
    const long long bo = (long long)(z / NHc) * p.BbO + (long long)(z % NHc) * p.BbI;
    const long long co = (long long)(z / NHc) * p.CbO + (long long)(z % NHc) * p.CbI;

    __shared__ float As[2][BK][BM];
    __shared__ float Bs[2][BK][BN];

    const int ar = tid >> 1;
    const int akk = (tid & 1) * 4;
    const int grr = i0 + ar;
    const float* Arow = p.A + ao + (long long)(grr / p.Arpc) * p.Achunk
                               + (long long)(grr % p.Arpc) * p.lda + akk;
    const float* Bbase = p.Bm + bo;
    const int br = BT ? (tid >> 1) : (tid / (BN / 4));
    const int bc = BT ? (tid & 1) * 4 : (tid % (BN / 4)) * 4;

    const int ry = (tid / (BN / TN)) * TM;
    const int rx = (tid % (BN / TN)) * TN;

    float acc[TM][TN] = {};

    const int kmax = p.kcausal ? ((i0 + BM < p.K) ? (i0 + BM) : p.K) : p.K;

    float4 va = *(const float4*)(Arow + 0);
    float4 vb;
    if (BT) vb = *(const float4*)(Bbase + (long long)(j0 + br) * p.ldb + bc);
    else    vb = *(const float4*)(Bbase + (long long)br * p.ldb + j0 + bc);
    As[0][akk + 0][ar] = va.x; As[0][akk + 1][ar] = va.y;
    As[0][akk + 2][ar] = va.z; As[0][akk + 3][ar] = va.w;
    if (BT) {
        Bs[0][bc + 0][br] = vb.x; Bs[0][bc + 1][br] = vb.y;
        Bs[0][bc + 2][br] = vb.z; Bs[0][bc + 3][br] = vb.w;
    } else {
        *(float4*)&Bs[0][br][bc] = vb;
    }
    __syncthreads();

    int buf = 0;
    for (int kb = 0; kb < kmax; kb += BK) {
        const int nkb = kb + BK;
        if (nkb < kmax) {
            va = *(const float4*)(Arow + nkb);
            if (BT) vb = *(const float4*)(Bbase + (long long)(j0 + br) * p.ldb + nkb + bc);
            else    vb = *(const float4*)(Bbase + (long long)(nkb + br) * p.ldb + j0 + bc);
        }
#pragma unroll
        for (int kk = 0; kk < BK; kk++) {
            float a[TM], b[TN];
#pragma unroll
            for (int i = 0; i < TM; i += 4)
                *(float4*)&a[i] = *(const float4*)&As[buf][kk][ry + i];
#pragma unroll
            for (int j = 0; j < TN; j += 4)
                *(float4*)&b[j] = *(const float4*)&Bs[buf][kk][rx + j];
#pragma unroll
            for (int i = 0; i < TM; i++)
#pragma unroll
                for (int j = 0; j < TN; j++)
                    acc[i][j] += a[i] * b[j];
        }
        if (nkb < kmax) {
            const int nb = buf ^ 1;
            As[nb][akk + 0][ar] = va.x; As[nb][akk + 1][ar] = va.y;
            As[nb][akk + 2][ar] = va.z; As[nb][akk + 3][ar] = va.w;
            if (BT) {
                Bs[nb][bc + 0][br] = vb.x; Bs[nb][bc + 1][br] = vb.y;
                Bs[nb][bc + 2][br] = vb.z; Bs[nb][bc + 3][br] = vb.w;
            } else {
                *(float4*)&Bs[nb][br][bc] = vb;
            }
            __syncthreads();
            buf = nb;
        }
    }

    float* C = p.C + co + (long long)i0 * p.ldc + j0;
#pragma unroll
    for (int ii = 0; ii < TM; ii++) {
        const int gi = i0 + ry + ii;
#pragma unroll
        for (int jj = 0; jj < TN; jj += 4) {
            float4 v = make_float4(acc[ii][jj], acc[ii][jj + 1],
                                   acc[ii][jj + 2], acc[ii][jj + 3]);
            const int gj = j0 + rx + jj;
            if (EPI == 1) {
                v.x = (gj + 0 > gi) ? -10000.0f : v.x * 0.125f;
                v.y = (gj + 1 > gi) ? -10000.0f : v.y * 0.125f;
                v.z = (gj + 2 > gi) ? -10000.0f : v.z * 0.125f;
                v.w = (gj + 3 > gi) ? -10000.0f : v.w * 0.125f;
            } else if (p.bias) {
                v.x += p.bias[gj + 0]; v.y += p.bias[gj + 1];
                v.z += p.bias[gj + 2]; v.w += p.bias[gj + 3];
            }
            *(float4*)(C + (long long)(ry + ii) * p.ldc + rx + jj) = v;
        }
    }
}

// ---------------- softmax for part-0 rows ---------------------------------
__global__ __launch_bounds__(256) void softmax0_k(float* sc) {
    const int row = blockIdx.x;
    const int bh = row / S0c;
    const int i  = row % S0c;
    float* p = sc + (long long)bh * S0c * S0c + (long long)i * S0c;
    const int len = i + 1;
    const int tid = threadIdx.x;
    __shared__ float red[256];

    float m = -1e30f;
    for (int j = tid; j < len; j += 256) m = fmaxf(m, p[j]);
    red[tid] = m; __syncthreads();
    for (int s = 128; s > 0; s >>= 1) {
        if (tid < s) red[tid] = fmaxf(red[tid], red[tid + s]);
        __syncthreads();
    }
    m = red[0]; __syncthreads();

    float sum = 0.f;
    for (int j = tid; j < len; j += 256) {
        float e = __expf(p[j] - m);
        p[j] = e;
        sum += e;
    }
    red[tid] = sum; __syncthreads();
    for (int s = 128; s > 0; s >>= 1) {
        if (tid < s) red[tid] += red[tid + s];
        __syncthreads();
    }
    const float inv = 1.0f / red[0];
    for (int j = tid; j < len; j += 256) p[j] *= inv;
    for (int j = len + tid; j < S0c; j += 256) p[j] = 0.f;
}

// ---------------- local attention (part 1): warp per position --------------
__global__ __launch_bounds__(256) void local_attn_k(const float* __restrict__ qkv0,
                                                    const float* __restrict__ qkv1,
                                                    float* __restrict__ ctx) {
    const int gwarp = (blockIdx.x * blockDim.x + threadIdx.x) >> 5;
    const int lane = threadIdx.x & 31;
    const int x  = gwarp & 63;
    const int y  = (gwarp >> 6) & 63;
    const int bh = gwarp >> 12;
    const int b = bh >> 4, h = bh & 15;

    const float* qp = qkv1 + ((long long)b * S1c + (y * 64 + x)) * H3 + h * HDc;
    float2 q = *(const float2*)(qp + lane * 2);
    q.x *= 0.125f; q.y *= 0.125f;

    const float* k0base = qkv0 + (long long)b * S0c * H3 + Hc + h * HDc;
    const float* k1base = qkv1 + (long long)b * S1c * H3 + Hc + h * HDc;
    const float* v0base = qkv0 + (long long)b * S0c * H3 + 2 * Hc + h * HDc;
    const float* v1base = qkv1 + (long long)b * S1c * H3 + 2 * Hc + h * HDc;

    float sreg[4] = {-1e30f, -1e30f, -1e30f, -1e30f};

#pragma unroll
    for (int o = 0; o < 49; o++) {
        const int dy = o / 7 - 3, dx = o % 7 - 3;
        const int yy = (y >> 1) + dy, xx = (x >> 1) + dx;
        float s = 0.f;
        if ((unsigned)yy < 32u && (unsigned)xx < 32u) {
            float2 k = *(const float2*)(k0base + (long long)(TEXTC + yy * 32 + xx) * H3 + lane * 2);
            float t = q.x * k.x + q.y * k.y;
            t += __shfl_xor_sync(0xffffffffu, t, 16);
            t += __shfl_xor_sync(0xffffffffu, t, 8);
            t += __shfl_xor_sync(0xffffffffu, t, 4);
            t += __shfl_xor_sync(0xffffffffu, t, 2);
            t += __shfl_xor_sync(0xffffffffu, t, 1);
            s = t;
        }
        if (lane == (o & 31)) sreg[o >> 5] = s;
    }
#pragma unroll
    for (int o = 49; o < 126; o++) {
        const int oc = o - 49;
        const int dy = oc / 9 - 8, dx = oc % 9 - 4;
        const int ny = y + dy, nx = x + dx;
        float s = 0.f;
        if ((unsigned)ny < 64u && (unsigned)nx < 64u) {
            float2 k = *(const float2*)(k1base + (long long)(ny * 64 + nx) * H3 + lane * 2);
            float t = q.x * k.x + q.y * k.y;
            t += __shfl_xor_sync(0xffffffffu, t, 16);
            t += __shfl_xor_sync(0xffffffffu, t, 8);
            t += __shfl_xor_sync(0xffffffffu, t, 4);
            t += __shfl_xor_sync(0xffffffffu, t, 2);
            t += __shfl_xor_sync(0xffffffffu, t, 1);
            s = t;
        }
        if (lane == (o & 31)) sreg[o >> 5] = s;
    }

    float m = fmaxf(fmaxf(sreg[0], sreg[1]), fmaxf(sreg[2], sreg[3]));
    m = fmaxf(m, __shfl_xor_sync(0xffffffffu, m, 16));
    m = fmaxf(m, __shfl_xor_sync(0xffffffffu, m, 8));
    m = fmaxf(m, __shfl_xor_sync(0xffffffffu, m, 4));
    m = fmaxf(m, __shfl_xor_sync(0xffffffffu, m, 2));
    m = fmaxf(m, __shfl_xor_sync(0xffffffffu, m, 1));
    float e0 = __expf(sreg[0] - m), e1 = __expf(sreg[1] - m);
    float e2 = __expf(sreg[2] - m), e3 = __expf(sreg[3] - m);
    float sum = e0 + e1 + e2 + e3;
    sum += __shfl_xor_sync(0xffffffffu, sum, 16);
    sum += __shfl_xor_sync(0xffffffffu, sum, 8);
    sum += __shfl_xor_sync(0xffffffffu, sum, 4);
    sum += __shfl_xor_sync(0xffffffffu, sum, 2);
    sum += __shfl_xor_sync(0xffffffffu, sum, 1);
    const float inv = 1.0f / sum;
    sreg[0] = e0 * inv; sreg[1] = e1 * inv; sreg[2] = e2 * inv; sreg[3] = e3 * inv;

    float2 out = make_float2(0.f, 0.f);
#pragma unroll
    for (int o = 0; o < 49; o++) {
        const int dy = o / 7 - 3, dx = o % 7 - 3;
        const int yy = (y >> 1) + dy, xx = (x >> 1) + dx;
        const float pw = __shfl_sync(0xffffffffu, sreg[o >> 5], o & 31);
        if ((unsigned)yy < 32u && (unsigned)xx < 32u) {
            float2 v = *(const float2*)(v0base + (long long)(TEXTC + yy * 32 + xx) * H3 + lane * 2);
            out.x += pw * v.x; out.y += pw * v.y;
        }
    }
#pragma unroll
    for (int o = 49; o < 126; o++) {
        const int oc = o - 49;
        const int dy = oc / 9 - 8, dx = oc % 9 - 4;
        const int ny = y + dy, nx = x + dx;
        const float pw = __shfl_sync(0xffffffffu, sreg[o >> 5], o & 31);
        if ((unsigned)ny < 64u && (unsigned)nx < 64u) {
            float2 v = *(const float2*)(v1base + (long long)(ny * 64 + nx) * H3 + lane * 2);
            out.x += pw * v.x; out.y += pw * v.y;
        }
    }

    float* cp = ctx + ((long long)b * Sc + S0c + y * 64 + x) * Hc + h * HDc;
    *(float2*)(cp + lane * 2) = out;
}

// ---------------- host launch ---------------------------------------------
extern "C" void kernel_launch(void* const* d_in, const int* in_sizes, int n_in,
                              void* d_out, int out_size) {
    const float* hidden  = (const float*)d_in[0];
    const float* W_qkv   = (const float*)d_in[2];
    const float* b_qkv   = (const float*)d_in[3];
    const float* W_qkvp  = (const float*)d_in[4];
    const float* b_qkvp  = (const float*)d_in[5];
    const float* W_dense = (const float*)d_in[6];
    const float* b_dense = (const float*)d_in[7];
    float* out = (float*)d_out;

    float *qkv0, *qkv1, *sc, *ctx;
    cudaGetSymbolAddress((void**)&qkv0, g_qkv0);
    cudaGetSymbolAddress((void**)&qkv1, g_qkv1);
    cudaGetSymbolAddress((void**)&sc, g_sc);
    cudaGetSymbolAddress((void**)&ctx, g_ctx);

    const int BIG = 1 << 30;

    // 1) QKV for part 0 (tf32 tensor cores)
    {
        GemmP p = {};
        p.A = hidden; p.Bm = W_qkv; p.C = qkv0; p.bias = b_qkv;
        p.K = Hc; p.lda = Hc; p.ldb = H3; p.ldc = H3;
        p.Arpc = S0c; p.Achunk = (long long)Sc * Hc;
        gemm_tf32_k<<<dim3(H3 / 128, Bn * S0c / 128, 1), 256>>>(p);
    }
    // 2) QKV for part 1 (tf32 tensor cores)
    {
        GemmP p = {};
        p.A = hidden + (long long)S0c * Hc; p.Bm = W_qkvp; p.C = qkv1; p.bias = b_qkvp;
        p.K = Hc; p.lda = Hc; p.ldb = H3; p.ldc = H3;
        p.Arpc = S1c; p.Achunk = (long long)Sc * Hc;
        gemm_tf32_k<<<dim3(H3 / 128, Bn * S1c / 128, 1), 256>>>(p);
    }
    // 3) scores0 = (Q0/8) @ K0^T, causal masked
    {
        GemmP p = {};
        p.A = qkv0; p.Bm = qkv0 + Hc; p.C = sc; p.bias = nullptr;
        p.K = HDc; p.lda = H3; p.ldb = H3; p.ldc = S0c;
        p.Arpc = BIG; p.Achunk = 0;
        p.AbO = (long long)S0c * H3; p.AbI = HDc;
        p.BbO = (long long)S0c * H3; p.BbI = HDc;
        p.CbO = (long long)NHc * S0c * S0c; p.CbI = (long long)S0c * S0c;
        gemm_k<64, 64, 8, 4, true, 1><<<dim3(S0c / 64, S0c / 64, Bn * NHc), 128>>>(p);
    }
    // 4) softmax (zeros above diagonal)
    softmax0_k<<<Bn * NHc * S0c, 256>>>(sc);
    // 5) context0 = P @ V0
    {
        GemmP p = {};
        p.A = sc; p.Bm = qkv0 + 2 * Hc; p.C = ctx; p.bias = nullptr;
        p.K = S0c; p.lda = S0c; p.ldb = H3; p.ldc = Hc;
        p.Arpc = BIG; p.Achunk = 0;
        p.AbO = (long long)NHc * S0c * S0c; p.AbI = (long long)S0c * S0c;
        p.BbO = (long long)S0c * H3; p.BbI = HDc;
        p.CbO = (long long)Sc * Hc; p.CbI = HDc;
        p.kcausal = 1;
        gemm_k<64, 64, 8, 4, false, 0><<<dim3(1, S0c / 64, Bn * NHc), 128>>>(p);
    }
    // 6) local attention part 1
    local_attn_k<<<(Bn * NHc * 64 * 64 * 32) / 256, 256>>>(qkv0, qkv1, ctx);
    // 7) out = ctx @ W_dense + b_dense (tf32 tensor cores)
    {
        GemmP p = {};
        p.A = ctx; p.Bm = W_dense; p.C = out; p.bias = b_dense;
        p.K = Hc; p.lda = Hc; p.ldb = Hc; p.ldc = Hc;
        p.Arpc = BIG; p.Achunk = 0;
        gemm_tf32_k<<<dim3(Hc / 128, Bn * Sc / 128, 1), 256>>>(p);
    }
}

// round 4
// speedup vs baseline: 1.3200x; 1.0204x over previous
#include <cuda_runtime.h>
#include <cstdint>

#define Bn   4
#define TEXTC 64
#define S0c  1088
#define S1c  4096
#define Sc   5184
#define Hc   1024
#define NHc  16
#define HDc  64
#define H3   3072

// ---------------- scratch (static device globals; no allocation) ----------
__device__ float g_qkv0[(size_t)Bn * S0c * H3];          // (B, S0, 3H)
__device__ float g_qkv1[(size_t)Bn * S1c * H3];          // (B, S1, 3H)
__device__ float g_ctx[(size_t)Bn * Sc * Hc];            // concat context

struct GemmP {
    const float* A; const float* Bm; float* C; const float* bias;
    int K;
    int lda, ldb, ldc;
    int Arpc;            // rows per chunk for A row mapping (batch folding)
    long long Achunk;    // chunk stride for A
};

__device__ __forceinline__ uint32_t f2tf32(float x) {
    uint32_t r;
    asm("cvt.rna.tf32.f32 %0, %1;" : "=r"(r) : "f"(x));
    return r;
}

#define MMA_TF32(d, a, b)                                                     \
    asm volatile(                                                             \
        "mma.sync.aligned.m16n8k8.row.col.f32.tf32.tf32.f32 "                 \
        "{%0,%1,%2,%3}, {%4,%5,%6,%7}, {%8,%9}, {%0,%1,%2,%3};\n"             \
        : "+f"(d[0]), "+f"(d[1]), "+f"(d[2]), "+f"(d[3])                      \
        : "r"(a[0]), "r"(a[1]), "r"(a[2]), "r"(a[3]), "r"(b[0]), "r"(b[1]))

// =================== tf32 tensor-core GEMM (plain, +bias) ==================
#define SA 136

__global__ __launch_bounds__(256) void gemm_tf32_k(GemmP p) {
    const int tid = threadIdx.x;
    const int i0 = blockIdx.y * 128;
    const int j0 = blockIdx.x * 128;

    __shared__ uint32_t As[2][16][SA];
    __shared__ uint32_t Bs[2][16][SA];

    const int am = tid & 127;
    const int ak = (tid >> 7) * 8;
    const int gr = i0 + am;
    const float* Arow = p.A + (long long)(gr / p.Arpc) * p.Achunk
                            + (long long)(gr % p.Arpc) * p.lda + ak;
    const int bn = (tid & 31) * 4;
    const int bk = tid >> 5;
    const float* Brow = p.Bm + (long long)bk * p.ldb + j0 + bn;

    const int lane = tid & 31;
    const int wid = tid >> 5;
    const int wm = (wid >> 2) * 64;
    const int wn = (wid & 3) * 32;
    const int lg = lane >> 2;
    const int lk = lane & 3;

    float acc[4][4][4] = {};

    float4 a0 = *(const float4*)(Arow + 0);
    float4 a1 = *(const float4*)(Arow + 4);
    float4 b0 = *(const float4*)(Brow);
    float4 b1 = *(const float4*)(Brow + 8 * p.ldb);
    {
        As[0][ak + 0][am] = f2tf32(a0.x); As[0][ak + 1][am] = f2tf32(a0.y);
        As[0][ak + 2][am] = f2tf32(a0.z); As[0][ak + 3][am] = f2tf32(a0.w);
        As[0][ak + 4][am] = f2tf32(a1.x); As[0][ak + 5][am] = f2tf32(a1.y);
        As[0][ak + 6][am] = f2tf32(a1.z); As[0][ak + 7][am] = f2tf32(a1.w);
        uint4 u0 = make_uint4(f2tf32(b0.x), f2tf32(b0.y), f2tf32(b0.z), f2tf32(b0.w));
        uint4 u1 = make_uint4(f2tf32(b1.x), f2tf32(b1.y), f2tf32(b1.z), f2tf32(b1.w));
        *(uint4*)&Bs[0][bk][bn]     = u0;
        *(uint4*)&Bs[0][bk + 8][bn] = u1;
    }
    __syncthreads();

    int buf = 0;
    for (int kb = 0; kb < p.K; kb += 16) {
        const int nkb = kb + 16;
        if (nkb < p.K) {
            a0 = *(const float4*)(Arow + nkb);
            a1 = *(const float4*)(Arow + nkb + 4);
            b0 = *(const float4*)(Brow + (long long)nkb * p.ldb);
            b1 = *(const float4*)(Brow + (long long)(nkb + 8) * p.ldb);
        }
#pragma unroll
        for (int ks = 0; ks < 16; ks += 8) {
            uint32_t af[4][4], bf[4][2];
#pragma unroll
            for (int mf = 0; mf < 4; mf++) {
                const int r0 = wm + mf * 16 + lg;
                af[mf][0] = As[buf][ks + lk][r0];
                af[mf][1] = As[buf][ks + lk][r0 + 8];
                af[mf][2] = As[buf][ks + 4 + lk][r0];
                af[mf][3] = As[buf][ks + 4 + lk][r0 + 8];
            }
#pragma unroll
            for (int nf = 0; nf < 4; nf++) {
                const int c0 = wn + nf * 8 + lg;
                bf[nf][0] = Bs[buf][ks + lk][c0];
                bf[nf][1] = Bs[buf][ks + 4 + lk][c0];
            }
#pragma unroll
            for (int mf = 0; mf < 4; mf++)
#pragma unroll
                for (int nf = 0; nf < 4; nf++) {
                    float* d = acc[mf][nf];
                    MMA_TF32(d, af[mf], bf[nf]);
                }
        }
        if (nkb < p.K) {
            const int nb = buf ^ 1;
            As[nb][ak + 0][am] = f2tf32(a0.x); As[nb][ak + 1][am] = f2tf32(a0.y);
            As[nb][ak + 2][am] = f2tf32(a0.z); As[nb][ak + 3][am] = f2tf32(a0.w);
            As[nb][ak + 4][am] = f2tf32(a1.x); As[nb][ak + 5][am] = f2tf32(a1.y);
            As[nb][ak + 6][am] = f2tf32(a1.z); As[nb][ak + 7][am] = f2tf32(a1.w);
            uint4 u0 = make_uint4(f2tf32(b0.x), f2tf32(b0.y), f2tf32(b0.z), f2tf32(b0.w));
            uint4 u1 = make_uint4(f2tf32(b1.x), f2tf32(b1.y), f2tf32(b1.z), f2tf32(b1.w));
            *(uint4*)&Bs[nb][bk][bn]     = u0;
            *(uint4*)&Bs[nb][bk + 8][bn] = u1;
            __syncthreads();
            buf = nb;
        }
    }

    float* C = p.C + (long long)i0 * p.ldc + j0;
#pragma unroll
    for (int mf = 0; mf < 4; mf++) {
#pragma unroll
        for (int nf = 0; nf < 4; nf++) {
            const int r = wm + mf * 16 + lg;
            const int c = wn + nf * 8 + (lk << 1);
            float bx = 0.f, by = 0.f;
            if (p.bias) { bx = p.bias[j0 + c]; by = p.bias[j0 + c + 1]; }
            float2 v0 = make_float2(acc[mf][nf][0] + bx, acc[mf][nf][1] + by);
            float2 v1 = make_float2(acc[mf][nf][2] + bx, acc[mf][nf][3] + by);
            *(float2*)(C + (long long)r * p.ldc + c)       = v0;
            *(float2*)(C + (long long)(r + 8) * p.ldc + c) = v1;
        }
    }
}

// =================== fused flash attention for part 0 ======================
// grid (S0/64, B*NH), 256 threads (8 warps: 4m x 2n over 64x64 tiles).
// Q tile resident; loop over causal K/V tiles; S via tf32 mma; online softmax;
// P routed through smem (transposed tf32) into P@V tf32 mma.
#define FS 68   // row stride for Qs/Ks/Vs/Ss
#define PS 69   // row stride for Pt (odd to limit transpose-store conflicts)

__global__ __launch_bounds__(256) void flash0_k(const float* __restrict__ qkv0,
                                                float* __restrict__ ctx) {
    extern __shared__ uint32_t sm[];
    uint32_t* Qs = sm;                    // [64][FS] (k=d major)
    uint32_t* Ks = Qs + 64 * FS;          // [64][FS] (k=d major)
    uint32_t* Vs = Ks + 64 * FS;          // [64][FS] (j major)
    float*    Ss = (float*)(Vs + 64 * FS);    // [64][FS] scores
    uint32_t* Pt = (uint32_t*)(Ss + 64 * FS); // [64][PS] (j major, transposed)
    float*    m_s = (float*)(Pt + 64 * PS);
    float*    l_s = m_s + 64;
    float*    f_s = l_s + 64;

    const int tid = threadIdx.x;
    const int z = blockIdx.y;
    const int b = z >> 4, h = z & 15;
    const int i0 = blockIdx.x * 64;

    const int lane = tid & 31;
    const int wid = tid >> 5;
    const int wm = (wid >> 1) * 16;    // warp m offset (rows)
    const int wn = (wid & 1) * 32;     // warp n offset (cols)
    const int lg = lane >> 2;
    const int lk = lane & 3;

    // loader mapping: thread owns one row, 16 of 64 dims
    const int lrow = tid & 63;
    const int d0 = (tid >> 6) * 16;

    const float* base = qkv0 + (long long)b * S0c * H3 + (long long)h * HDc;

    // load Q (scaled by 1/8), transposed into Qs[d][row]
    {
        const float* qr = base + (long long)(i0 + lrow) * H3 + d0;
#pragma unroll
        for (int q4 = 0; q4 < 4; q4++) {
            float4 v = *(const float4*)(qr + q4 * 4);
            Qs[(d0 + q4 * 4 + 0) * FS + lrow] = f2tf32(v.x * 0.125f);
            Qs[(d0 + q4 * 4 + 1) * FS + lrow] = f2tf32(v.y * 0.125f);
            Qs[(d0 + q4 * 4 + 2) * FS + lrow] = f2tf32(v.z * 0.125f);
            Qs[(d0 + q4 * 4 + 3) * FS + lrow] = f2tf32(v.w * 0.125f);
        }
    }
    if (tid < 64) { m_s[tid] = -1e30f; l_s[tid] = 0.f; }

    float oacc[4][4] = {};
    const int jtiles = i0 / 64 + 1;

    for (int jt = 0; jt < jtiles; jt++) {
        const int j0 = jt * 64;
        // load K (transposed) and V (natural) tiles
        {
            const float* kr = base + Hc + (long long)(j0 + lrow) * H3 + d0;
            const float* vr = base + 2 * Hc + (long long)(j0 + lrow) * H3 + d0;
#pragma unroll
            for (int q4 = 0; q4 < 4; q4++) {
                float4 v = *(const float4*)(kr + q4 * 4);
                Ks[(d0 + q4 * 4 + 0) * FS + lrow] = f2tf32(v.x);
                Ks[(d0 + q4 * 4 + 1) * FS + lrow] = f2tf32(v.y);
                Ks[(d0 + q4 * 4 + 2) * FS + lrow] = f2tf32(v.z);
                Ks[(d0 + q4 * 4 + 3) * FS + lrow] = f2tf32(v.w);
                float4 w = *(const float4*)(vr + q4 * 4);
                uint4 u = make_uint4(f2tf32(w.x), f2tf32(w.y), f2tf32(w.z), f2tf32(w.w));
                *(uint4*)&Vs[lrow * FS + d0 + q4 * 4] = u;
            }
        }
        __syncthreads();

        // S = Q @ K^T for this tile (warp tile 16x32)
        {
            float sacc[4][4] = {};
#pragma unroll
            for (int ks = 0; ks < 64; ks += 8) {
                uint32_t af[4], bf[4][2];
                const int r0 = wm + lg;
                af[0] = Qs[(ks + lk) * FS + r0];
                af[1] = Qs[(ks + lk) * FS + r0 + 8];
                af[2] = Qs[(ks + 4 + lk) * FS + r0];
                af[3] = Qs[(ks + 4 + lk) * FS + r0 + 8];
#pragma unroll
                for (int nf = 0; nf < 4; nf++) {
                    const int c0 = wn + nf * 8 + lg;
                    bf[nf][0] = Ks[(ks + lk) * FS + c0];
                    bf[nf][1] = Ks[(ks + 4 + lk) * FS + c0];
                }
#pragma unroll
                for (int nf = 0; nf < 4; nf++) {
                    float* d = sacc[nf];
                    MMA_TF32(d, af, bf[nf]);
                }
            }
            const int r0 = wm + lg;
#pragma unroll
            for (int nf = 0; nf < 4; nf++) {
                const int c = wn + nf * 8 + lk * 2;
                Ss[r0 * FS + c]           = sacc[nf][0];
                Ss[r0 * FS + c + 1]       = sacc[nf][1];
                Ss[(r0 + 8) * FS + c]     = sacc[nf][2];
                Ss[(r0 + 8) * FS + c + 1] = sacc[nf][3];
            }
        }
        __syncthreads();

        // online softmax row pass: 4 threads per row, 16 cols each
        {
            const int trow = tid >> 2;
            const int cb = (tid & 3) * 16;
            const int gi = i0 + trow;
            float sv[16];
            float tm = -1e30f;
#pragma unroll
            for (int t = 0; t < 16; t++) {
                const int c = cb + t;
                float s = Ss[trow * FS + c];
                if (j0 + c > gi) s = -10000.0f;
                sv[t] = s;
                tm = fmaxf(tm, s);
            }
            tm = fmaxf(tm, __shfl_xor_sync(0xffffffffu, tm, 1));
            tm = fmaxf(tm, __shfl_xor_sync(0xffffffffu, tm, 2));
            const float mo = m_s[trow];
            const float mn = fmaxf(mo, tm);
            const float f = __expf(mo - mn);
            float psum = 0.f;
#pragma unroll
            for (int t = 0; t < 16; t++) {
                float e = __expf(sv[t] - mn);
                Pt[(cb + t) * PS + trow] = f2tf32(e);
                psum += e;
            }
            psum += __shfl_xor_sync(0xffffffffu, psum, 1);
            psum += __shfl_xor_sync(0xffffffffu, psum, 2);
            if ((tid & 3) == 0) {
                m_s[trow] = mn;
                l_s[trow] = l_s[trow] * f + psum;
                f_s[trow] = f;
            }
        }
        __syncthreads();

        // O = O * f + P @ V (warp tile 16x32 over 64x64 O)
        {
            const int r0 = wm + lg;
            const float f0 = f_s[r0];
            const float f1 = f_s[r0 + 8];
#pragma unroll
            for (int nf = 0; nf < 4; nf++) {
                oacc[nf][0] *= f0; oacc[nf][1] *= f0;
                oacc[nf][2] *= f1; oacc[nf][3] *= f1;
            }
#pragma unroll
            for (int ks = 0; ks < 64; ks += 8) {
                uint32_t af[4], bf[4][2];
                af[0] = Pt[(ks + lk) * PS + r0];
                af[1] = Pt[(ks + lk) * PS + r0 + 8];
                af[2] = Pt[(ks + 4 + lk) * PS + r0];
                af[3] = Pt[(ks + 4 + lk) * PS + r0 + 8];
#pragma unroll
                for (int nf = 0; nf < 4; nf++) {
                    const int c0 = wn + nf * 8 + lg;
                    bf[nf][0] = Vs[(ks + lk) * FS + c0];
                    bf[nf][1] = Vs[(ks + 4 + lk) * FS + c0];
                }
#pragma unroll
                for (int nf = 0; nf < 4; nf++) {
                    float* d = oacc[nf];
                    MMA_TF32(d, af, bf[nf]);
                }
            }
        }
        __syncthreads();
    }

    // epilogue: normalize and write to ctx
    {
        const int r0 = wm + lg;
        const float inv0 = 1.0f / l_s[r0];
        const float inv1 = 1.0f / l_s[r0 + 8];
        float* c0p = ctx + ((long long)b * Sc + i0 + r0) * Hc + h * HDc;
        float* c1p = ctx + ((long long)b * Sc + i0 + r0 + 8) * Hc + h * HDc;
#pragma unroll
        for (int nf = 0; nf < 4; nf++) {
            const int c = wn + nf * 8 + lk * 2;
            *(float2*)(c0p + c) = make_float2(oacc[nf][0] * inv0, oacc[nf][1] * inv0);
            *(float2*)(c1p + c) = make_float2(oacc[nf][2] * inv1, oacc[nf][3] * inv1);
        }
    }
}

// ---------------- local attention (part 1): warp per position --------------
__global__ __launch_bounds__(256) void local_attn_k(const float* __restrict__ qkv0,
                                                    const float* __restrict__ qkv1,
                                                    float* __restrict__ ctx) {
    const int gwarp = (blockIdx.x * blockDim.x + threadIdx.x) >> 5;
    const int lane = threadIdx.x & 31;
    const int x  = gwarp & 63;
    const int y  = (gwarp >> 6) & 63;
    const int bh = gwarp >> 12;
    const int b = bh >> 4, h = bh & 15;

    const float* qp = qkv1 + ((long long)b * S1c + (y * 64 + x)) * H3 + h * HDc;
    float2 q = *(const float2*)(qp + lane * 2);
    q.x *= 0.125f; q.y *= 0.125f;

    const float* k0base = qkv0 + (long long)b * S0c * H3 + Hc + h * HDc;
    const float* k1base = qkv1 + (long long)b * S1c * H3 + Hc + h * HDc;
    const float* v0base = qkv0 + (long long)b * S0c * H3 + 2 * Hc + h * HDc;
    const float* v1base = qkv1 + (long long)b * S1c * H3 + 2 * Hc + h * HDc;

    float sreg[4] = {-1e30f, -1e30f, -1e30f, -1e30f};

#pragma unroll
    for (int o = 0; o < 49; o++) {
        const int dy = o / 7 - 3, dx = o % 7 - 3;
        const int yy = (y >> 1) + dy, xx = (x >> 1) + dx;
        float s = 0.f;
        if ((unsigned)yy < 32u && (unsigned)xx < 32u) {
            float2 k = *(const float2*)(k0base + (long long)(TEXTC + yy * 32 + xx) * H3 + lane * 2);
            float t = q.x * k.x + q.y * k.y;
            t += __shfl_xor_sync(0xffffffffu, t, 16);
            t += __shfl_xor_sync(0xffffffffu, t, 8);
            t += __shfl_xor_sync(0xffffffffu, t, 4);
            t += __shfl_xor_sync(0xffffffffu, t, 2);
            t += __shfl_xor_sync(0xffffffffu, t, 1);
            s = t;
        }
        if (lane == (o & 31)) sreg[o >> 5] = s;
    }
#pragma unroll
    for (int o = 49; o < 126; o++) {
        const int oc = o - 49;
        const int dy = oc / 9 - 8, dx = oc % 9 - 4;
        const int ny = y + dy, nx = x + dx;
        float s = 0.f;
        if ((unsigned)ny < 64u && (unsigned)nx < 64u) {
            float2 k = *(const float2*)(k1base + (long long)(ny * 64 + nx) * H3 + lane * 2);
            float t = q.x * k.x + q.y * k.y;
            t += __shfl_xor_sync(0xffffffffu, t, 16);
            t += __shfl_xor_sync(0xffffffffu, t, 8);
            t += __shfl_xor_sync(0xffffffffu, t, 4);
            t += __shfl_xor_sync(0xffffffffu, t, 2);
            t += __shfl_xor_sync(0xffffffffu, t, 1);
            s = t;
        }
        if (lane == (o & 31)) sreg[o >> 5] = s;
    }

    float m = fmaxf(fmaxf(sreg[0], sreg[1]), fmaxf(sreg[2], sreg[3]));
    m = fmaxf(m, __shfl_xor_sync(0xffffffffu, m, 16));
    m = fmaxf(m, __shfl_xor_sync(0xffffffffu, m, 8));
    m = fmaxf(m, __shfl_xor_sync(0xffffffffu, m, 4));
    m = fmaxf(m, __shfl_xor_sync(0xffffffffu, m, 2));
    m = fmaxf(m, __shfl_xor_sync(0xffffffffu, m, 1));
    float e0 = __expf(sreg[0] - m), e1 = __expf(sreg[1] - m);
    float e2 = __expf(sreg[2] - m), e3 = __expf(sreg[3] - m);
    float sum = e0 + e1 + e2 + e3;
    sum += __shfl_xor_sync(0xffffffffu, sum, 16);
    sum += __shfl_xor_sync(0xffffffffu, sum, 8);
    sum += __shfl_xor_sync(0xffffffffu, sum, 4);
    sum += __shfl_xor_sync(0xffffffffu, sum, 2);
    sum += __shfl_xor_sync(0xffffffffu, sum, 1);
    const float inv = 1.0f / sum;
    sreg[0] = e0 * inv; sreg[1] = e1 * inv; sreg[2] = e2 * inv; sreg[3] = e3 * inv;

    float2 out = make_float2(0.f, 0.f);
#pragma unroll
    for (int o = 0; o < 49; o++) {
        const int dy = o / 7 - 3, dx = o % 7 - 3;
        const int yy = (y >> 1) + dy, xx = (x >> 1) + dx;
        const float pw = __shfl_sync(0xffffffffu, sreg[o >> 5], o & 31);
        if ((unsigned)yy < 32u && (unsigned)xx < 32u) {
            float2 v = *(const float2*)(v0base + (long long)(TEXTC + yy * 32 + xx) * H3 + lane * 2);
            out.x += pw * v.x; out.y += pw * v.y;
        }
    }
#pragma unroll
    for (int o = 49; o < 126; o++) {
        const int oc = o - 49;
        const int dy = oc / 9 - 8, dx = oc % 9 - 4;
        const int ny = y + dy, nx = x + dx;
        const float pw = __shfl_sync(0xffffffffu, sreg[o >> 5], o & 31);
        if ((unsigned)ny < 64u && (unsigned)nx < 64u) {
            float2 v = *(const float2*)(v1base + (long long)(ny * 64 + nx) * H3 + lane * 2);
            out.x += pw * v.x; out.y += pw * v.y;
        }
    }

    float* cp = ctx + ((long long)b * Sc + S0c + y * 64 + x) * Hc + h * HDc;
    *(float2*)(cp + lane * 2) = out;
}

// ---------------- host launch ---------------------------------------------
extern "C" void kernel_launch(void* const* d_in, const int* in_sizes, int n_in,
                              void* d_out, int out_size) {
    const float* hidden  = (const float*)d_in[0];
    const float* W_qkv   = (const float*)d_in[2];
    const float* b_qkv   = (const float*)d_in[3];
    const float* W_qkvp  = (const float*)d_in[4];
    const float* b_qkvp  = (const float*)d_in[5];
    const float* W_dense = (const float*)d_in[6];
    const float* b_dense = (const float*)d_in[7];
    float* out = (float*)d_out;

    float *qkv0, *qkv1, *ctx;
    cudaGetSymbolAddress((void**)&qkv0, g_qkv0);
    cudaGetSymbolAddress((void**)&qkv1, g_qkv1);
    cudaGetSymbolAddress((void**)&ctx, g_ctx);

    const int BIG = 1 << 30;
    const int flash_smem = (3 * 64 * FS + 64 * FS + 64 * PS + 192) * 4;
    static int attr_done = 0;
    if (!attr_done) {
        cudaFuncSetAttribute(flash0_k, cudaFuncAttributeMaxDynamicSharedMemorySize,
                             flash_smem);
        attr_done = 1;
    }

    // 1) QKV for part 0 (tf32)
    {
        GemmP p = {};
        p.A = hidden; p.Bm = W_qkv; p.C = qkv0; p.bias = b_qkv;
        p.K = Hc; p.lda = Hc; p.ldb = H3; p.ldc = H3;
        p.Arpc = S0c; p.Achunk = (long long)Sc * Hc;
        gemm_tf32_k<<<dim3(H3 / 128, Bn * S0c / 128, 1), 256>>>(p);
    }
    // 2) QKV for part 1 (tf32)
    {
        GemmP p = {};
        p.A = hidden + (long long)S0c * Hc; p.Bm = W_qkvp; p.C = qkv1; p.bias = b_qkvp;
        p.K = Hc; p.lda = Hc; p.ldb = H3; p.ldc = H3;
        p.Arpc = S1c; p.Achunk = (long long)Sc * Hc;
        gemm_tf32_k<<<dim3(H3 / 128, Bn * S1c / 128, 1), 256>>>(p);
    }
    // 3) fused flash attention for part 0
    flash0_k<<<dim3(S0c / 64, Bn * NHc), 256, flash_smem>>>(qkv0, ctx);
    // 4) local attention part 1
    local_attn_k<<<(Bn * NHc * 64 * 64 * 32) / 256, 256>>>(qkv0, qkv1, ctx);
    // 5) out = ctx @ W_dense + b_dense (tf32)
    {
        GemmP p = {};
        p.A = ctx; p.Bm = W_dense; p.C = out; p.bias = b_dense;
        p.K = Hc; p.lda = Hc; p.ldb = Hc; p.ldc = Hc;
        p.Arpc = BIG; p.Achunk = 0;
        gemm_tf32_k<<<dim3(Hc / 128, Bn * Sc / 128, 1), 256>>>(p);
    }
}

// round 6
// speedup vs baseline: 3.1918x; 2.4180x over previous
#include <cuda_runtime.h>
#include <cuda_fp16.h>
#include <cstdint>

#define Bn   4
#define TEXTC 64
#define S0c  1088
#define S1c  4096
#define Sc   5184
#define Hc   1024
#define NHc  16
#define HDc  64
#define H3   3072

// ---------------- scratch (static device globals; no allocation) ----------
__device__ float g_qkv0[(size_t)Bn * S0c * H3];          // (B, S0, 3H)
__device__ float g_qkv1[(size_t)Bn * S1c * H3];          // (B, S1, 3H)
__device__ float g_ctx[(size_t)Bn * Sc * Hc];            // concat context

struct GemmP {
    const float* A; const float* Bm; float* C; const float* bias;
    int K;
    int lda, ldb, ldc;
    int Arpc;            // rows per chunk for A row mapping (batch folding)
    long long Achunk;    // chunk stride for A
};

__device__ __forceinline__ uint32_t f2tf32(float x) {
    uint32_t r;
    asm("cvt.rna.tf32.f32 %0, %1;" : "=r"(r) : "f"(x));
    return r;
}

#define MMA_TF32(d, a, b)                                                     \
    asm volatile(                                                             \
        "mma.sync.aligned.m16n8k8.row.col.f32.tf32.tf32.f32 "                 \
        "{%0,%1,%2,%3}, {%4,%5,%6,%7}, {%8,%9}, {%0,%1,%2,%3};\n"             \
        : "+f"(d[0]), "+f"(d[1]), "+f"(d[2]), "+f"(d[3])                      \
        : "r"(a[0]), "r"(a[1]), "r"(a[2]), "r"(a[3]), "r"(b[0]), "r"(b[1]))

#define MMA_F16(d, a, b)                                                      \
    asm volatile(                                                             \
        "mma.sync.aligned.m16n8k16.row.col.f32.f16.f16.f32 "                  \
        "{%0,%1,%2,%3}, {%4,%5,%6,%7}, {%8,%9}, {%0,%1,%2,%3};\n"             \
        : "+f"(d[0]), "+f"(d[1]), "+f"(d[2]), "+f"(d[3])                      \
        : "r"(a[0]), "r"(a[1]), "r"(a[2]), "r"(a[3]), "r"(b[0]), "r"(b[1]))

__device__ __forceinline__ void ldmat_x4(uint32_t* r, uint32_t saddr) {
    asm volatile("ldmatrix.sync.aligned.m8n8.x4.shared.b16 {%0,%1,%2,%3}, [%4];"
                 : "=r"(r[0]), "=r"(r[1]), "=r"(r[2]), "=r"(r[3]) : "r"(saddr));
}
__device__ __forceinline__ void ldmat_x4t(uint32_t* r, uint32_t saddr) {
    asm volatile("ldmatrix.sync.aligned.m8n8.x4.trans.shared.b16 {%0,%1,%2,%3}, [%4];"
                 : "=r"(r[0]), "=r"(r[1]), "=r"(r[2]), "=r"(r[3]) : "r"(saddr));
}

__device__ __forceinline__ uint32_t h2pack(float x, float y) {
    __half2 h = __floats2half2_rn(x, y);
    return *(uint32_t*)&h;
}

// =================== fp16 tensor-core GEMM (C=f32, +bias) ==================
// tile 128x128x16, 256 threads (8 warps: 2m x 4n, warp tile 64x32)
#define ASTR 24    // A smem row stride in halves (48B)
#define BSTR 136   // B smem row stride in halves (272B)

__global__ __launch_bounds__(256) void gemm_f16_k(GemmP p) {
    const int tid = threadIdx.x;
    const int i0 = blockIdx.y * 128;
    const int j0 = blockIdx.x * 128;

    __shared__ __align__(16) __half As[2][128][ASTR];
    __shared__ __align__(16) __half Bs[2][16][BSTR];

    // A loader: thread owns row am, k-halves [ak, ak+8)
    const int am = tid & 127;
    const int ak = (tid >> 7) * 8;
    const int gr = i0 + am;
    const float* Arow = p.A + (long long)(gr / p.Arpc) * p.Achunk
                            + (long long)(gr % p.Arpc) * p.lda + ak;
    // B loader: thread owns k-row bk, 8 columns at bn
    const int bk = tid >> 4;
    const int bn = (tid & 15) * 8;
    const float* Brow = p.Bm + (long long)bk * p.ldb + j0 + bn;

    const int lane = tid & 31;
    const int wid = tid >> 5;
    const int wm = (wid >> 2) * 64;
    const int wn = (wid & 3) * 32;

    // ldmatrix lane addresses
    const int a_r = lane & 15;
    const int a_c = (lane >> 4) * 8;
    const int b_r = ((lane >> 3) & 1) * 8 + (lane & 7);
    const int b_c = (lane >> 4) * 8;

    float acc[4][4][4] = {};

    float4 a0 = *(const float4*)(Arow + 0);
    float4 a1 = *(const float4*)(Arow + 4);
    float4 b0 = *(const float4*)(Brow);
    float4 b1 = *(const float4*)(Brow + 4);
    {
        uint4 ua = make_uint4(h2pack(a0.x, a0.y), h2pack(a0.z, a0.w),
                              h2pack(a1.x, a1.y), h2pack(a1.z, a1.w));
        *(uint4*)&As[0][am][ak] = ua;
        uint4 ub = make_uint4(h2pack(b0.x, b0.y), h2pack(b0.z, b0.w),
                              h2pack(b1.x, b1.y), h2pack(b1.z, b1.w));
        *(uint4*)&Bs[0][bk][bn] = ub;
    }
    __syncthreads();

    int buf = 0;
    for (int kb = 0; kb < p.K; kb += 16) {
        const int nkb = kb + 16;
        if (nkb < p.K) {
            a0 = *(const float4*)(Arow + nkb);
            a1 = *(const float4*)(Arow + nkb + 4);
            b0 = *(const float4*)(Brow + (long long)nkb * p.ldb);
            b1 = *(const float4*)(Brow + (long long)nkb * p.ldb + 4);
        }
        // fragments
        uint32_t af[4][4], bf[8];
#pragma unroll
        for (int mf = 0; mf < 4; mf++) {
            uint32_t sa = (uint32_t)__cvta_generic_to_shared(
                &As[buf][wm + mf * 16 + a_r][a_c]);
            ldmat_x4(af[mf], sa);
        }
#pragma unroll
        for (int nb = 0; nb < 2; nb++) {
            uint32_t sb = (uint32_t)__cvta_generic_to_shared(
                &Bs[buf][b_r][wn + nb * 16 + b_c]);
            ldmat_x4t(&bf[nb * 4], sb);
        }
#pragma unroll
        for (int mf = 0; mf < 4; mf++)
#pragma unroll
            for (int nf = 0; nf < 4; nf++) {
                float* d = acc[mf][nf];
                const uint32_t* bb = &bf[(nf >> 1) * 4 + (nf & 1) * 2];
                MMA_F16(d, af[mf], bb);
            }
        if (nkb < p.K) {
            const int nb2 = buf ^ 1;
            uint4 ua = make_uint4(h2pack(a0.x, a0.y), h2pack(a0.z, a0.w),
                                  h2pack(a1.x, a1.y), h2pack(a1.z, a1.w));
            *(uint4*)&As[nb2][am][ak] = ua;
            uint4 ub = make_uint4(h2pack(b0.x, b0.y), h2pack(b0.z, b0.w),
                                  h2pack(b1.x, b1.y), h2pack(b1.z, b1.w));
            *(uint4*)&Bs[nb2][bk][bn] = ub;
            __syncthreads();
            buf = nb2;
        }
    }

    const int lg = lane >> 2;
    const int lk = lane & 3;
    float* C = p.C + (long long)i0 * p.ldc + j0;
#pragma unroll
    for (int mf = 0; mf < 4; mf++) {
#pragma unroll
        for (int nf = 0; nf < 4; nf++) {
            const int r = wm + mf * 16 + lg;
            const int c = wn + nf * 8 + (lk << 1);
            float bx = 0.f, by = 0.f;
            if (p.bias) { bx = p.bias[j0 + c]; by = p.bias[j0 + c + 1]; }
            float2 v0 = make_float2(acc[mf][nf][0] + bx, acc[mf][nf][1] + by);
            float2 v1 = make_float2(acc[mf][nf][2] + bx, acc[mf][nf][3] + by);
            *(float2*)(C + (long long)r * p.ldc + c)       = v0;
            *(float2*)(C + (long long)(r + 8) * p.ldc + c) = v1;
        }
    }
}

// =================== fused flash attention for part 0 (tf32) ===============
#define FS 68
#define PS 69

__global__ __launch_bounds__(256) void flash0_k(const float* __restrict__ qkv0,
                                                float* __restrict__ ctx) {
    extern __shared__ uint32_t sm[];
    uint32_t* Qs = sm;
    uint32_t* Ks = Qs + 64 * FS;
    uint32_t* Vs = Ks + 64 * FS;
    float*    Ss = (float*)(Vs + 64 * FS);
    uint32_t* Pt = (uint32_t*)(Ss + 64 * FS);
    float*    m_s = (float*)(Pt + 64 * PS);
    float*    l_s = m_s + 64;
    float*    f_s = l_s + 64;

    const int tid = threadIdx.x;
    const int z = blockIdx.y;
    const int b = z >> 4, h = z & 15;
    const int i0 = blockIdx.x * 64;

    const int lane = tid & 31;
    const int wid = tid >> 5;
    const int wm = (wid >> 1) * 16;
    const int wn = (wid & 1) * 32;
    const int lg = lane >> 2;
    const int lk = lane & 3;

    const int lrow = tid & 63;
    const int d0 = (tid >> 6) * 16;

    const float* base = qkv0 + (long long)b * S0c * H3 + (long long)h * HDc;

    {
        const float* qr = base + (long long)(i0 + lrow) * H3 + d0;
#pragma unroll
        for (int q4 = 0; q4 < 4; q4++) {
            float4 v = *(const float4*)(qr + q4 * 4);
            Qs[(d0 + q4 * 4 + 0) * FS + lrow] = f2tf32(v.x * 0.125f);
            Qs[(d0 + q4 * 4 + 1) * FS + lrow] = f2tf32(v.y * 0.125f);
            Qs[(d0 + q4 * 4 + 2) * FS + lrow] = f2tf32(v.z * 0.125f);
            Qs[(d0 + q4 * 4 + 3) * FS + lrow] = f2tf32(v.w * 0.125f);
        }
    }
    if (tid < 64) { m_s[tid] = -1e30f; l_s[tid] = 0.f; }

    float oacc[4][4] = {};
    const int jtiles = i0 / 64 + 1;

    for (int jt = 0; jt < jtiles; jt++) {
        const int j0 = jt * 64;
        {
            const float* kr = base + Hc + (long long)(j0 + lrow) * H3 + d0;
            const float* vr = base + 2 * Hc + (long long)(j0 + lrow) * H3 + d0;
#pragma unroll
            for (int q4 = 0; q4 < 4; q4++) {
                float4 v = *(const float4*)(kr + q4 * 4);
                Ks[(d0 + q4 * 4 + 0) * FS + lrow] = f2tf32(v.x);
                Ks[(d0 + q4 * 4 + 1) * FS + lrow] = f2tf32(v.y);
                Ks[(d0 + q4 * 4 + 2) * FS + lrow] = f2tf32(v.z);
                Ks[(d0 + q4 * 4 + 3) * FS + lrow] = f2tf32(v.w);
                float4 w = *(const float4*)(vr + q4 * 4);
                uint4 u = make_uint4(f2tf32(w.x), f2tf32(w.y), f2tf32(w.z), f2tf32(w.w));
                *(uint4*)&Vs[lrow * FS + d0 + q4 * 4] = u;
            }
        }
        __syncthreads();

        {
            float sacc[4][4] = {};
#pragma unroll
            for (int ks = 0; ks < 64; ks += 8) {
                uint32_t af[4], bf[4][2];
                const int r0 = wm + lg;
                af[0] = Qs[(ks + lk) * FS + r0];
                af[1] = Qs[(ks + lk) * FS + r0 + 8];
                af[2] = Qs[(ks + 4 + lk) * FS + r0];
                af[3] = Qs[(ks + 4 + lk) * FS + r0 + 8];
#pragma unroll
                for (int nf = 0; nf < 4; nf++) {
                    const int c0 = wn + nf * 8 + lg;
                    bf[nf][0] = Ks[(ks + lk) * FS + c0];
                    bf[nf][1] = Ks[(ks + 4 + lk) * FS + c0];
                }
#pragma unroll
                for (int nf = 0; nf < 4; nf++) {
                    float* d = sacc[nf];
                    MMA_TF32(d, af, bf[nf]);
                }
            }
            const int r0 = wm + lg;
#pragma unroll
            for (int nf = 0; nf < 4; nf++) {
                const int c = wn + nf * 8 + lk * 2;
                Ss[r0 * FS + c]           = sacc[nf][0];
                Ss[r0 * FS + c + 1]       = sacc[nf][1];
                Ss[(r0 + 8) * FS + c]     = sacc[nf][2];
                Ss[(r0 + 8) * FS + c + 1] = sacc[nf][3];
            }
        }
        __syncthreads();

        {
            const int trow = tid >> 2;
            const int cb = (tid & 3) * 16;
            const int gi = i0 + trow;
            float sv[16];
            float tm = -1e30f;
#pragma unroll
            for (int t = 0; t < 16; t++) {
                const int c = cb + t;
                float s = Ss[trow * FS + c];
                if (j0 + c > gi) s = -10000.0f;
                sv[t] = s;
                tm = fmaxf(tm, s);
            }
            tm = fmaxf(tm, __shfl_xor_sync(0xffffffffu, tm, 1));
            tm = fmaxf(tm, __shfl_xor_sync(0xffffffffu, tm, 2));
            const float mo = m_s[trow];
            const float mn = fmaxf(mo, tm);
            const float f = __expf(mo - mn);
            float psum = 0.f;
#pragma unroll
            for (int t = 0; t < 16; t++) {
                float e = __expf(sv[t] - mn);
                Pt[(cb + t) * PS + trow] = f2tf32(e);
                psum += e;
            }
            psum += __shfl_xor_sync(0xffffffffu, psum, 1);
            psum += __shfl_xor_sync(0xffffffffu, psum, 2);
            if ((tid & 3) == 0) {
                m_s[trow] = mn;
                l_s[trow] = l_s[trow] * f + psum;
                f_s[trow] = f;
            }
        }
        __syncthreads();

        {
            const int r0 = wm + lg;
            const float f0 = f_s[r0];
            const float f1 = f_s[r0 + 8];
#pragma unroll
            for (int nf = 0; nf < 4; nf++) {
                oacc[nf][0] *= f0; oacc[nf][1] *= f0;
                oacc[nf][2] *= f1; oacc[nf][3] *= f1;
            }
#pragma unroll
            for (int ks = 0; ks < 64; ks += 8) {
                uint32_t af[4], bf[4][2];
                af[0] = Pt[(ks + lk) * PS + r0];
                af[1] = Pt[(ks + lk) * PS + r0 + 8];
                af[2] = Pt[(ks + 4 + lk) * PS + r0];
                af[3] = Pt[(ks + 4 + lk) * PS + r0 + 8];
#pragma unroll
                for (int nf = 0; nf < 4; nf++) {
                    const int c0 = wn + nf * 8 + lg;
                    bf[nf][0] = Vs[(ks + lk) * FS + c0];
                    bf[nf][1] = Vs[(ks + 4 + lk) * FS + c0];
                }
#pragma unroll
                for (int nf = 0; nf < 4; nf++) {
                    float* d = oacc[nf];
                    MMA_TF32(d, af, bf[nf]);
                }
            }
        }
        __syncthreads();
    }

    {
        const int r0 = wm + lg;
        const float inv0 = 1.0f / l_s[r0];
        const float inv1 = 1.0f / l_s[r0 + 8];
        float* c0p = ctx + ((long long)b * Sc + i0 + r0) * Hc + h * HDc;
        float* c1p = ctx + ((long long)b * Sc + i0 + r0 + 8) * Hc + h * HDc;
#pragma unroll
        for (int nf = 0; nf < 4; nf++) {
            const int c = wn + nf * 8 + lk * 2;
            *(float2*)(c0p + c) = make_float2(oacc[nf][0] * inv0, oacc[nf][1] * inv0);
            *(float2*)(c1p + c) = make_float2(oacc[nf][2] * inv1, oacc[nf][3] * inv1);
        }
    }
}

// ---------------- local attention (part 1): warp/position, smem scores -----
__global__ __launch_bounds__(256) void local_attn_k(const float* __restrict__ qkv0,
                                                    const float* __restrict__ qkv1,
                                                    float* __restrict__ ctx) {
    __shared__ float ssc[8][128];

    const int w = threadIdx.x >> 5;
    const int lane = threadIdx.x & 31;
    const int gwarp = blockIdx.x * 8 + w;
    const int x  = gwarp & 63;
    const int y  = (gwarp >> 6) & 63;
    const int bh = gwarp >> 12;
    const int b = bh >> 4, h = bh & 15;

    const float* qp = qkv1 + ((long long)b * S1c + (y * 64 + x)) * H3 + h * HDc;
    float2 q = *(const float2*)(qp + lane * 2);
    q.x *= 0.125f; q.y *= 0.125f;

    const float* k0base = qkv0 + (long long)b * S0c * H3 + Hc + h * HDc;
    const float* k1base = qkv1 + (long long)b * S1c * H3 + Hc + h * HDc;
    const float* v0base = qkv0 + (long long)b * S0c * H3 + 2 * Hc + h * HDc;
    const float* v1base = qkv1 + (long long)b * S1c * H3 + 2 * Hc + h * HDc;

    // phase 1: scores into smem
#pragma unroll 2
    for (int o = 0; o < 49; o++) {
        const int dy = o / 7 - 3, dx = o % 7 - 3;
        const int yy = (y >> 1) + dy, xx = (x >> 1) + dx;
        float t = 0.f;
        if ((unsigned)yy < 32u && (unsigned)xx < 32u) {
            float2 k = *(const float2*)(k0base + (long long)(TEXTC + yy * 32 + xx) * H3 + lane * 2);
            t = q.x * k.x + q.y * k.y;
        }
        t += __shfl_xor_sync(0xffffffffu, t, 16);
        t += __shfl_xor_sync(0xffffffffu, t, 8);
        t += __shfl_xor_sync(0xffffffffu, t, 4);
        t += __shfl_xor_sync(0xffffffffu, t, 2);
        t += __shfl_xor_sync(0xffffffffu, t, 1);
        if (lane == 0) ssc[w][o] = t;
    }
#pragma unroll 2
    for (int o = 49; o < 126; o++) {
        const int oc = o - 49;
        const int dy = oc / 9 - 8, dx = oc % 9 - 4;
        const int ny = y + dy, nx = x + dx;
        float t = 0.f;
        if ((unsigned)ny < 64u && (unsigned)nx < 64u) {
            float2 k = *(const float2*)(k1base + (long long)(ny * 64 + nx) * H3 + lane * 2);
            t = q.x * k.x + q.y * k.y;
        }
        t += __shfl_xor_sync(0xffffffffu, t, 16);
        t += __shfl_xor_sync(0xffffffffu, t, 8);
        t += __shfl_xor_sync(0xffffffffu, t, 4);
        t += __shfl_xor_sync(0xffffffffu, t, 2);
        t += __shfl_xor_sync(0xffffffffu, t, 1);
        if (lane == 0) ssc[w][o] = t;
    }
    __syncwarp();

    // phase 2: softmax over 126 values (4 per lane)
    float s0 = ssc[w][lane];
    float s1 = ssc[w][lane + 32];
    float s2 = ssc[w][lane + 64];
    float s3 = (lane + 96 < 126) ? ssc[w][lane + 96] : -1e30f;
    float m = fmaxf(fmaxf(s0, s1), fmaxf(s2, s3));
    m = fmaxf(m, __shfl_xor_sync(0xffffffffu, m, 16));
    m = fmaxf(m, __shfl_xor_sync(0xffffffffu, m, 8));
    m = fmaxf(m, __shfl_xor_sync(0xffffffffu, m, 4));
    m = fmaxf(m, __shfl_xor_sync(0xffffffffu, m, 2));
    m = fmaxf(m, __shfl_xor_sync(0xffffffffu, m, 1));
    float e0 = __expf(s0 - m), e1 = __expf(s1 - m);
    float e2 = __expf(s2 - m), e3 = (lane + 96 < 126) ? __expf(s3 - m) : 0.f;
    float sum = e0 + e1 + e2 + e3;
    sum += __shfl_xor_sync(0xffffffffu, sum, 16);
    sum += __shfl_xor_sync(0xffffffffu, sum, 8);
    sum += __shfl_xor_sync(0xffffffffu, sum, 4);
    sum += __shfl_xor_sync(0xffffffffu, sum, 2);
    sum += __shfl_xor_sync(0xffffffffu, sum, 1);
    const float inv = 1.0f / sum;
    ssc[w][lane]      = e0;
    ssc[w][lane + 32] = e1;
    ssc[w][lane + 64] = e2;
    if (lane + 96 < 126) ssc[w][lane + 96] = e3;
    __syncwarp();

    // phase 3: weighted V accumulation (normalize at the end)
    float2 out = make_float2(0.f, 0.f);
#pragma unroll 2
    for (int o = 0; o < 49; o++) {
        const int dy = o / 7 - 3, dx = o % 7 - 3;
        const int yy = (y >> 1) + dy, xx = (x >> 1) + dx;
        if ((unsigned)yy < 32u && (unsigned)xx < 32u) {
            const float pw = ssc[w][o];
            float2 v = *(const float2*)(v0base + (long long)(TEXTC + yy * 32 + xx) * H3 + lane * 2);
            out.x += pw * v.x; out.y += pw * v.y;
        }
    }
#pragma unroll 2
    for (int o = 49; o < 126; o++) {
        const int oc = o - 49;
        const int dy = oc / 9 - 8, dx = oc % 9 - 4;
        const int ny = y + dy, nx = x + dx;
        if ((unsigned)ny < 64u && (unsigned)nx < 64u) {
            const float pw = ssc[w][o];
            float2 v = *(const float2*)(v1base + (long long)(ny * 64 + nx) * H3 + lane * 2);
            out.x += pw * v.x; out.y += pw * v.y;
        }
    }
    out.x *= inv; out.y *= inv;

    float* cp = ctx + ((long long)b * Sc + S0c + y * 64 + x) * Hc + h * HDc;
    *(float2*)(cp + lane * 2) = out;
}

// ---------------- host launch ---------------------------------------------
extern "C" void kernel_launch(void* const* d_in, const int* in_sizes, int n_in,
                              void* d_out, int out_size) {
    const float* hidden  = (const float*)d_in[0];
    const float* W_qkv   = (const float*)d_in[2];
    const float* b_qkv   = (const float*)d_in[3];
    const float* W_qkvp  = (const float*)d_in[4];
    const float* b_qkvp  = (const float*)d_in[5];
    const float* W_dense = (const float*)d_in[6];
    const float* b_dense = (const float*)d_in[7];
    float* out = (float*)d_out;

    float *qkv0, *qkv1, *ctx;
    cudaGetSymbolAddress((void**)&qkv0, g_qkv0);
    cudaGetSymbolAddress((void**)&qkv1, g_qkv1);
    cudaGetSymbolAddress((void**)&ctx, g_ctx);

    const int BIG = 1 << 30;
    const int flash_smem = (3 * 64 * FS + 64 * FS + 64 * PS + 192) * 4;
    cudaFuncSetAttribute(flash0_k, cudaFuncAttributeMaxDynamicSharedMemorySize,
                         flash_smem);

    // 1) QKV for part 0 (fp16 TC)
    {
        GemmP p = {};
        p.A = hidden; p.Bm = W_qkv; p.C = qkv0; p.bias = b_qkv;
        p.K = Hc; p.lda = Hc; p.ldb = H3; p.ldc = H3;
        p.Arpc = S0c; p.Achunk = (long long)Sc * Hc;
        gemm_f16_k<<<dim3(H3 / 128, Bn * S0c / 128, 1), 256>>>(p);
    }
    // 2) QKV for part 1 (fp16 TC)
    {
        GemmP p = {};
        p.A = hidden + (long long)S0c * Hc; p.Bm = W_qkvp; p.C = qkv1; p.bias = b_qkvp;
        p.K = Hc; p.lda = Hc; p.ldb = H3; p.ldc = H3;
        p.Arpc = S1c; p.Achunk = (long long)Sc * Hc;
        gemm_f16_k<<<dim3(H3 / 128, Bn * S1c / 128, 1), 256>>>(p);
    }
    // 3) fused flash attention for part 0
    flash0_k<<<dim3(S0c / 64, Bn * NHc), 256, flash_smem>>>(qkv0, ctx);
    // 4) local attention part 1
    local_attn_k<<<Bn * NHc * 64 * 64 / 8, 256>>>(qkv0, qkv1, ctx);
    // 5) out = ctx @ W_dense + b_dense (fp16 TC)
    {
        GemmP p = {};
        p.A = ctx; p.Bm = W_dense; p.C = out; p.bias = b_dense;
        p.K = Hc; p.lda = Hc; p.ldb = Hc; p.ldc = Hc;
        p.Arpc = BIG; p.Achunk = 0;
        gemm_f16_k<<<dim3(Hc / 128, Bn * Sc / 128, 1), 256>>>(p);
    }
}

// round 7
// speedup vs baseline: 3.5640x; 1.1166x over previous
#include <cuda_runtime.h>
#include <cuda_fp16.h>
#include <cstdint>

#define Bn   4
#define TEXTC 64
#define S0c  1088
#define S1c  4096
#define Sc   5184
#define Hc   1024
#define NHc  16
#define HDc  64
#define H3   3072

// ---------------- scratch (static device globals; no allocation) ----------
__device__ __half g_h16[(size_t)Bn * Sc * Hc];            // hidden fp16
__device__ __half g_w16[(size_t)Hc * H3 * 2 + (size_t)Hc * Hc]; // Wqkv|Wqkvp|Wdense
__device__ __half g_qkv0h[(size_t)Bn * S0c * H3];
__device__ __half g_qkv1h[(size_t)Bn * S1c * H3];
__device__ __half g_ctx16[(size_t)Bn * Sc * Hc];

struct Gemm16P {
    const __half* A; const __half* Bm; void* C; const float* bias;
    int K;
    int lda, ldb, ldc;       // in halves (ldc in elements of C's type)
    int Arpc;                // rows per chunk (batch folding)
    long long Achunk;
};

#define MMA_F16(d, a, b)                                                      \
    asm volatile(                                                             \
        "mma.sync.aligned.m16n8k16.row.col.f32.f16.f16.f32 "                  \
        "{%0,%1,%2,%3}, {%4,%5,%6,%7}, {%8,%9}, {%0,%1,%2,%3};\n"             \
        : "+f"(d[0]), "+f"(d[1]), "+f"(d[2]), "+f"(d[3])                      \
        : "r"(a[0]), "r"(a[1]), "r"(a[2]), "r"(a[3]), "r"(b[0]), "r"(b[1]))

__device__ __forceinline__ void ldmat_x4(uint32_t* r, const void* ptr) {
    uint32_t s = (uint32_t)__cvta_generic_to_shared(ptr);
    asm volatile("ldmatrix.sync.aligned.m8n8.x4.shared.b16 {%0,%1,%2,%3}, [%4];"
                 : "=r"(r[0]), "=r"(r[1]), "=r"(r[2]), "=r"(r[3]) : "r"(s));
}
__device__ __forceinline__ void ldmat_x4t(uint32_t* r, const void* ptr) {
    uint32_t s = (uint32_t)__cvta_generic_to_shared(ptr);
    asm volatile("ldmatrix.sync.aligned.m8n8.x4.trans.shared.b16 {%0,%1,%2,%3}, [%4];"
                 : "=r"(r[0]), "=r"(r[1]), "=r"(r[2]), "=r"(r[3]) : "r"(s));
}
__device__ __forceinline__ void cp_async16(void* dst, const void* src) {
    uint32_t d = (uint32_t)__cvta_generic_to_shared(dst);
    asm volatile("cp.async.cg.shared.global [%0], [%1], 16;\n" :: "r"(d), "l"(src));
}
#define CP_COMMIT() asm volatile("cp.async.commit_group;\n")
#define CP_WAIT1()  asm volatile("cp.async.wait_group 1;\n")

__device__ __forceinline__ uint32_t h2pack(float x, float y) {
    __half2 h = __floats2half2_rn(x, y);
    return *(uint32_t*)&h;
}

// ---------------- fp32 -> fp16 convert (grid-stride over float4) ----------
__global__ void cvt16_k(const float4* __restrict__ src, uint2* __restrict__ dst,
                        int n4) {
    for (int i = blockIdx.x * blockDim.x + threadIdx.x; i < n4;
         i += gridDim.x * blockDim.x) {
        float4 v = src[i];
        dst[i] = make_uint2(h2pack(v.x, v.y), h2pack(v.z, v.w));
    }
}

// =================== fp16-in tensor-core GEMM, cp.async 3-stage ============
// tile 128x128x16, 256 threads (8 warps: 2m x 4n, warp tile 64x32)
#define ASTR 24    // A smem row stride in halves (48B)
#define BSTR 136   // B smem row stride in halves (272B)

template <int OUTH>
__global__ __launch_bounds__(256) void gemm16_k(Gemm16P p) {
    const int tid = threadIdx.x;
    const int i0 = blockIdx.y * 128;
    const int j0 = blockIdx.x * 128;

    __shared__ __align__(16) __half As[3][128][ASTR];
    __shared__ __align__(16) __half Bs[3][16][BSTR];

    // A loader: thread owns row am, halves [ak, ak+8)
    const int am = tid & 127;
    const int ak = (tid >> 7) * 8;
    const int gr = i0 + am;
    const __half* Asrc = p.A + (long long)(gr / p.Arpc) * p.Achunk
                             + (long long)(gr % p.Arpc) * p.lda + ak;
    // B loader: thread owns k-row bk, 8 columns at bn
    const int bk = tid >> 4;
    const int bn = (tid & 15) * 8;
    const __half* Bsrc = p.Bm + (long long)bk * p.ldb + j0 + bn;

    const int lane = tid & 31;
    const int wid = tid >> 5;
    const int wm = (wid >> 2) * 64;
    const int wn = (wid & 3) * 32;
    const int a_r = lane & 15;
    const int a_c = (lane >> 4) * 8;
    const int b_r = ((lane >> 3) & 1) * 8 + (lane & 7);
    const int b_c = (lane >> 4) * 8;

    float acc[4][4][4] = {};

    // prologue: stages 0,1
    cp_async16(&As[0][am][ak], Asrc);
    cp_async16(&Bs[0][bk][bn], Bsrc);
    CP_COMMIT();
    cp_async16(&As[1][am][ak], Asrc + 16);
    cp_async16(&Bs[1][bk][bn], Bsrc + (long long)16 * p.ldb);
    CP_COMMIT();
    CP_WAIT1();
    __syncthreads();

    int buf = 0;
    for (int kb = 0; kb < p.K; kb += 16) {
        const int pk = kb + 32;
        const int pbuf = (buf + 2) % 3;
        if (pk < p.K) {
            cp_async16(&As[pbuf][am][ak], Asrc + pk);
            cp_async16(&Bs[pbuf][bk][bn], Bsrc + (long long)pk * p.ldb);
        }
        CP_COMMIT();

        uint32_t af[4][4], bf[8];
#pragma unroll
        for (int mf = 0; mf < 4; mf++)
            ldmat_x4(af[mf], &As[buf][wm + mf * 16 + a_r][a_c]);
#pragma unroll
        for (int nb = 0; nb < 2; nb++)
            ldmat_x4t(&bf[nb * 4], &Bs[buf][b_r][wn + nb * 16 + b_c]);
#pragma unroll
        for (int mf = 0; mf < 4; mf++)
#pragma unroll
            for (int nf = 0; nf < 4; nf++) {
                float* d = acc[mf][nf];
                const uint32_t* bb = &bf[(nf >> 1) * 4 + (nf & 1) * 2];
                MMA_F16(d, af[mf], bb);
            }

        CP_WAIT1();
        __syncthreads();
        buf = (buf + 1) % 3;
    }

    const int lg = lane >> 2;
    const int lk = lane & 3;
#pragma unroll
    for (int mf = 0; mf < 4; mf++) {
#pragma unroll
        for (int nf = 0; nf < 4; nf++) {
            const int r = wm + mf * 16 + lg;
            const int c = wn + nf * 8 + (lk << 1);
            float bx = 0.f, by = 0.f;
            if (p.bias) { bx = p.bias[j0 + c]; by = p.bias[j0 + c + 1]; }
            float v00 = acc[mf][nf][0] + bx, v01 = acc[mf][nf][1] + by;
            float v10 = acc[mf][nf][2] + bx, v11 = acc[mf][nf][3] + by;
            if (OUTH) {
                __half* C = (__half*)p.C + (long long)i0 * p.ldc + j0;
                *(uint32_t*)(C + (long long)r * p.ldc + c)       = h2pack(v00, v01);
                *(uint32_t*)(C + (long long)(r + 8) * p.ldc + c) = h2pack(v10, v11);
            } else {
                float* C = (float*)p.C + (long long)i0 * p.ldc + j0;
                *(float2*)(C + (long long)r * p.ldc + c)       = make_float2(v00, v01);
                *(float2*)(C + (long long)(r + 8) * p.ldc + c) = make_float2(v10, v11);
            }
        }
    }
}

// =================== fused flash attention for part 0 (fp16 mma) ===========
#define FSH 72   // half stride for Qs/Ks/Vs/Ps
#define SSW 68   // float stride for Ss

__global__ __launch_bounds__(256) void flash0_k(const __half* __restrict__ qkv0h,
                                                __half* __restrict__ ctx16) {
    extern __shared__ __half smh[];
    __half* Qs = smh;                    // [64][FSH]
    __half* Ks = Qs + 64 * FSH;
    __half* Vs = Ks + 64 * FSH;
    __half* Ps = Vs + 64 * FSH;
    float*  Ss = (float*)(Ps + 64 * FSH);  // [64][SSW]
    float*  m_s = Ss + 64 * SSW;
    float*  l_s = m_s + 64;
    float*  f_s = l_s + 64;

    const int tid = threadIdx.x;
    const int z = blockIdx.y;
    const int b = z >> 4, h = z & 15;
    const int i0 = blockIdx.x * 64;

    const int lane = tid & 31;
    const int wid = tid >> 5;
    const int wm = (wid >> 1) * 16;
    const int wn = (wid & 1) * 32;
    const int lg = lane >> 2;
    const int lk = lane & 3;
    const int a_r = lane & 15;
    const int a_c = (lane >> 4) * 8;
    const int b_r = ((lane >> 3) & 1) * 8 + (lane & 7);
    const int b_c = (lane >> 4) * 8;

    const int lrow = tid & 63;
    const int d0 = (tid >> 6) * 16;

    const __half* base = qkv0h + (long long)b * S0c * H3 + (long long)h * HDc;

    // Q load (scale by 1/8, exact in fp16)
    {
        const __half* qr = base + (long long)(i0 + lrow) * H3 + d0;
        const __half2 sc8 = __floats2half2_rn(0.125f, 0.125f);
#pragma unroll
        for (int u = 0; u < 2; u++) {
            uint4 v = *(const uint4*)(qr + u * 8);
            __half2* hp = (__half2*)&v;
#pragma unroll
            for (int t = 0; t < 4; t++) hp[t] = __hmul2(hp[t], sc8);
            *(uint4*)&Qs[lrow * FSH + d0 + u * 8] = v;
        }
    }
    if (tid < 64) { m_s[tid] = -1e30f; l_s[tid] = 0.f; }

    float oacc[4][4] = {};
    const int jtiles = i0 / 64 + 1;

    for (int jt = 0; jt < jtiles; jt++) {
        const int j0 = jt * 64;
        {
            const __half* kr = base + Hc + (long long)(j0 + lrow) * H3 + d0;
            const __half* vr = base + 2 * Hc + (long long)(j0 + lrow) * H3 + d0;
#pragma unroll
            for (int u = 0; u < 2; u++) {
                *(uint4*)&Ks[lrow * FSH + d0 + u * 8] = *(const uint4*)(kr + u * 8);
                *(uint4*)&Vs[lrow * FSH + d0 + u * 8] = *(const uint4*)(vr + u * 8);
            }
        }
        __syncthreads();

        // S = Q @ K^T (warp tile 16x32); B from n-major Ks via non-trans ldmatrix
        {
            float sacc[4][4] = {};
#pragma unroll
            for (int ks = 0; ks < 64; ks += 16) {
                uint32_t af[4], kf[2][4];
                ldmat_x4(af, &Qs[(wm + a_r) * FSH + ks + a_c]);
#pragma unroll
                for (int nb = 0; nb < 2; nb++)
                    ldmat_x4(kf[nb], &Ks[(wn + nb * 16 + a_r) * FSH + ks + a_c]);
#pragma unroll
                for (int nf = 0; nf < 4; nf++) {
                    const int nb = nf >> 1, lo = nf & 1;
                    uint32_t bb[2] = { kf[nb][lo], kf[nb][lo + 2] };
                    float* d = sacc[nf];
                    MMA_F16(d, af, bb);
                }
            }
            const int r0 = wm + lg;
#pragma unroll
            for (int nf = 0; nf < 4; nf++) {
                const int c = wn + nf * 8 + lk * 2;
                Ss[r0 * SSW + c]           = sacc[nf][0];
                Ss[r0 * SSW + c + 1]       = sacc[nf][1];
                Ss[(r0 + 8) * SSW + c]     = sacc[nf][2];
                Ss[(r0 + 8) * SSW + c + 1] = sacc[nf][3];
            }
        }
        __syncthreads();

        // online softmax: 4 threads/row, 16 cols each; write P as fp16 row-major
        {
            const int trow = tid >> 2;
            const int cb = (tid & 3) * 16;
            const int gi = i0 + trow;
            float sv[16];
            float tm = -1e30f;
#pragma unroll
            for (int t = 0; t < 16; t++) {
                const int c = cb + t;
                float s = Ss[trow * SSW + c];
                if (j0 + c > gi) s = -10000.0f;
                sv[t] = s;
                tm = fmaxf(tm, s);
            }
            tm = fmaxf(tm, __shfl_xor_sync(0xffffffffu, tm, 1));
            tm = fmaxf(tm, __shfl_xor_sync(0xffffffffu, tm, 2));
            const float mo = m_s[trow];
            const float mn = fmaxf(mo, tm);
            const float f = __expf(mo - mn);
            float psum = 0.f;
#pragma unroll
            for (int t = 0; t < 16; t += 2) {
                float e0 = __expf(sv[t] - mn);
                float e1 = __expf(sv[t + 1] - mn);
                *(uint32_t*)&Ps[trow * FSH + cb + t] = h2pack(e0, e1);
                psum += e0 + e1;
            }
            psum += __shfl_xor_sync(0xffffffffu, psum, 1);
            psum += __shfl_xor_sync(0xffffffffu, psum, 2);
            if ((tid & 3) == 0) {
                m_s[trow] = mn;
                l_s[trow] = l_s[trow] * f + psum;
                f_s[trow] = f;
            }
        }
        __syncthreads();

        // O = O * f + P @ V
        {
            const int r0 = wm + lg;
            const float f0 = f_s[r0];
            const float f1 = f_s[r0 + 8];
#pragma unroll
            for (int nf = 0; nf < 4; nf++) {
                oacc[nf][0] *= f0; oacc[nf][1] *= f0;
                oacc[nf][2] *= f1; oacc[nf][3] *= f1;
            }
#pragma unroll
            for (int ks = 0; ks < 64; ks += 16) {
                uint32_t af[4], vf[2][4];
                ldmat_x4(af, &Ps[(wm + a_r) * FSH + ks + a_c]);
#pragma unroll
                for (int nb = 0; nb < 2; nb++)
                    ldmat_x4t(vf[nb], &Vs[(ks + b_r) * FSH + wn + nb * 16 + b_c]);
#pragma unroll
                for (int nf = 0; nf < 4; nf++) {
                    const int nb = nf >> 1;
                    const uint32_t* bb = &vf[nb][(nf & 1) * 2];
                    float* d = oacc[nf];
                    MMA_F16(d, af, bb);
                }
            }
        }
        __syncthreads();
    }

    // epilogue: normalize, write fp16 ctx
    {
        const int r0 = wm + lg;
        const float inv0 = 1.0f / l_s[r0];
        const float inv1 = 1.0f / l_s[r0 + 8];
        __half* c0p = ctx16 + ((long long)b * Sc + i0 + r0) * Hc + h * HDc;
        __half* c1p = ctx16 + ((long long)b * Sc + i0 + r0 + 8) * Hc + h * HDc;
#pragma unroll
        for (int nf = 0; nf < 4; nf++) {
            const int c = wn + nf * 8 + lk * 2;
            *(uint32_t*)(c0p + c) = h2pack(oacc[nf][0] * inv0, oacc[nf][1] * inv0);
            *(uint32_t*)(c1p + c) = h2pack(oacc[nf][2] * inv1, oacc[nf][3] * inv1);
        }
    }
}

// ---------------- local attention (part 1): warp/position, fp16 reads ------
__global__ __launch_bounds__(256) void local_attn_k(const __half* __restrict__ qkv0h,
                                                    const __half* __restrict__ qkv1h,
                                                    __half* __restrict__ ctx16) {
    __shared__ float ssc[8][128];

    const int w = threadIdx.x >> 5;
    const int lane = threadIdx.x & 31;
    const int gwarp = blockIdx.x * 8 + w;
    const int x  = gwarp & 63;
    const int y  = (gwarp >> 6) & 63;
    const int bh = gwarp >> 12;
    const int b = bh >> 4, h = bh & 15;

    const __half* qp = qkv1h + ((long long)b * S1c + (y * 64 + x)) * H3 + h * HDc;
    float2 q = __half22float2(*(const __half2*)(qp + lane * 2));
    q.x *= 0.125f; q.y *= 0.125f;

    const __half* k0base = qkv0h + (long long)b * S0c * H3 + Hc + h * HDc;
    const __half* k1base = qkv1h + (long long)b * S1c * H3 + Hc + h * HDc;
    const __half* v0base = qkv0h + (long long)b * S0c * H3 + 2 * Hc + h * HDc;
    const __half* v1base = qkv1h + (long long)b * S1c * H3 + 2 * Hc + h * HDc;

    // phase 1: scores into smem
#pragma unroll 2
    for (int o = 0; o < 49; o++) {
        const int dy = o / 7 - 3, dx = o % 7 - 3;
        const int yy = (y >> 1) + dy, xx = (x >> 1) + dx;
        float t = 0.f;
        if ((unsigned)yy < 32u && (unsigned)xx < 32u) {
            float2 k = __half22float2(*(const __half2*)(
                k0base + (long long)(TEXTC + yy * 32 + xx) * H3 + lane * 2));
            t = q.x * k.x + q.y * k.y;
        }
        t += __shfl_xor_sync(0xffffffffu, t, 16);
        t += __shfl_xor_sync(0xffffffffu, t, 8);
        t += __shfl_xor_sync(0xffffffffu, t, 4);
        t += __shfl_xor_sync(0xffffffffu, t, 2);
        t += __shfl_xor_sync(0xffffffffu, t, 1);
        if (lane == 0) ssc[w][o] = t;
    }
#pragma unroll 2
    for (int o = 49; o < 126; o++) {
        const int oc = o - 49;
        const int dy = oc / 9 - 8, dx = oc % 9 - 4;
        const int ny = y + dy, nx = x + dx;
        float t = 0.f;
        if ((unsigned)ny < 64u && (unsigned)nx < 64u) {
            float2 k = __half22float2(*(const __half2*)(
                k1base + (long long)(ny * 64 + nx) * H3 + lane * 2));
            t = q.x * k.x + q.y * k.y;
        }
        t += __shfl_xor_sync(0xffffffffu, t, 16);
        t += __shfl_xor_sync(0xffffffffu, t, 8);
        t += __shfl_xor_sync(0xffffffffu, t, 4);
        t += __shfl_xor_sync(0xffffffffu, t, 2);
        t += __shfl_xor_sync(0xffffffffu, t, 1);
        if (lane == 0) ssc[w][o] = t;
    }
    __syncwarp();

    // phase 2: softmax over 126 values
    float s0 = ssc[w][lane];
    float s1 = ssc[w][lane + 32];
    float s2 = ssc[w][lane + 64];
    float s3 = (lane + 96 < 126) ? ssc[w][lane + 96] : -1e30f;
    float m = fmaxf(fmaxf(s0, s1), fmaxf(s2, s3));
    m = fmaxf(m, __shfl_xor_sync(0xffffffffu, m, 16));
    m = fmaxf(m, __shfl_xor_sync(0xffffffffu, m, 8));
    m = fmaxf(m, __shfl_xor_sync(0xffffffffu, m, 4));
    m = fmaxf(m, __shfl_xor_sync(0xffffffffu, m, 2));
    m = fmaxf(m, __shfl_xor_sync(0xffffffffu, m, 1));
    float e0 = __expf(s0 - m), e1 = __expf(s1 - m);
    float e2 = __expf(s2 - m), e3 = (lane + 96 < 126) ? __expf(s3 - m) : 0.f;
    float sum = e0 + e1 + e2 + e3;
    sum += __shfl_xor_sync(0xffffffffu, sum, 16);
    sum += __shfl_xor_sync(0xffffffffu, sum, 8);
    sum += __shfl_xor_sync(0xffffffffu, sum, 4);
    sum += __shfl_xor_sync(0xffffffffu, sum, 2);
    sum += __shfl_xor_sync(0xffffffffu, sum, 1);
    const float inv = 1.0f / sum;
    ssc[w][lane]      = e0;
    ssc[w][lane + 32] = e1;
    ssc[w][lane + 64] = e2;
    if (lane + 96 < 126) ssc[w][lane + 96] = e3;
    __syncwarp();

    // phase 3: weighted V accumulation
    float2 out = make_float2(0.f, 0.f);
#pragma unroll 2
    for (int o = 0; o < 49; o++) {
        const int dy = o / 7 - 3, dx = o % 7 - 3;
        const int yy = (y >> 1) + dy, xx = (x >> 1) + dx;
        if ((unsigned)yy < 32u && (unsigned)xx < 32u) {
            const float pw = ssc[w][o];
            float2 v = __half22float2(*(const __half2*)(
                v0base + (long long)(TEXTC + yy * 32 + xx) * H3 + lane * 2));
            out.x += pw * v.x; out.y += pw * v.y;
        }
    }
#pragma unroll 2
    for (int o = 49; o < 126; o++) {
        const int oc = o - 49;
        const int dy = oc / 9 - 8, dx = oc % 9 - 4;
        const int ny = y + dy, nx = x + dx;
        if ((unsigned)ny < 64u && (unsigned)nx < 64u) {
            const float pw = ssc[w][o];
            float2 v = __half22float2(*(const __half2*)(
                v1base + (long long)(ny * 64 + nx) * H3 + lane * 2));
            out.x += pw * v.x; out.y += pw * v.y;
        }
    }
    out.x *= inv; out.y *= inv;

    __half* cp = ctx16 + ((long long)b * Sc + S0c + y * 64 + x) * Hc + h * HDc;
    *(uint32_t*)(cp + lane * 2) = h2pack(out.x, out.y);
}

// ---------------- host launch ---------------------------------------------
extern "C" void kernel_launch(void* const* d_in, const int* in_sizes, int n_in,
                              void* d_out, int out_size) {
    const float* hidden  = (const float*)d_in[0];
    const float* W_qkv   = (const float*)d_in[2];
    const float* b_qkv   = (const float*)d_in[3];
    const float* W_qkvp  = (const float*)d_in[4];
    const float* b_qkvp  = (const float*)d_in[5];
    const float* W_dense = (const float*)d_in[6];
    const float* b_dense = (const float*)d_in[7];
    float* out = (float*)d_out;

    __half *h16, *w16, *qkv0h, *qkv1h, *ctx16;
    cudaGetSymbolAddress((void**)&h16, g_h16);
    cudaGetSymbolAddress((void**)&w16, g_w16);
    cudaGetSymbolAddress((void**)&qkv0h, g_qkv0h);
    cudaGetSymbolAddress((void**)&qkv1h, g_qkv1h);
    cudaGetSymbolAddress((void**)&ctx16, g_ctx16);

    const int BIG = 1 << 30;
    const int flash_smem = 4 * 64 * FSH * 2 + 64 * SSW * 4 + 3 * 64 * 4;
    cudaFuncSetAttribute(flash0_k, cudaFuncAttributeMaxDynamicSharedMemorySize,
                         flash_smem);

    // 0) converts
    {
        int n4 = Bn * Sc * Hc / 4;
        cvt16_k<<<2048, 256>>>((const float4*)hidden, (uint2*)h16, n4);
        n4 = Hc * H3 / 4;
        cvt16_k<<<1024, 256>>>((const float4*)W_qkv, (uint2*)w16, n4);
        cvt16_k<<<1024, 256>>>((const float4*)W_qkvp,
                               (uint2*)(w16 + (size_t)Hc * H3), n4);
        n4 = Hc * Hc / 4;
        cvt16_k<<<512, 256>>>((const float4*)W_dense,
                              (uint2*)(w16 + (size_t)2 * Hc * H3), n4);
    }
    // 1) QKV part 0 (fp16 out)
    {
        Gemm16P p = {};
        p.A = h16; p.Bm = w16; p.C = qkv0h; p.bias = b_qkv;
        p.K = Hc; p.lda = Hc; p.ldb = H3; p.ldc = H3;
        p.Arpc = S0c; p.Achunk = (long long)Sc * Hc;
        gemm16_k<1><<<dim3(H3 / 128, Bn * S0c / 128, 1), 256>>>(p);
    }
    // 2) QKV part 1 (fp16 out)
    {
        Gemm16P p = {};
        p.A = h16 + (long long)S0c * Hc; p.Bm = w16 + (size_t)Hc * H3;
        p.C = qkv1h; p.bias = b_qkvp;
        p.K = Hc; p.lda = Hc; p.ldb = H3; p.ldc = H3;
        p.Arpc = S1c; p.Achunk = (long long)Sc * Hc;
        gemm16_k<1><<<dim3(H3 / 128, Bn * S1c / 128, 1), 256>>>(p);
    }
    // 3) fused flash attention for part 0
    flash0_k<<<dim3(S0c / 64, Bn * NHc), 256, flash_smem>>>(qkv0h, ctx16);
    // 4) local attention part 1
    local_attn_k<<<Bn * NHc * 64 * 64 / 8, 256>>>(qkv0h, qkv1h, ctx16);
    // 5) out = ctx @ W_dense + b_dense (fp32 out)
    {
        Gemm16P p = {};
        p.A = ctx16; p.Bm = w16 + (size_t)2 * Hc * H3; p.C = out; p.bias = b_dense;
        p.K = Hc; p.lda = Hc; p.ldb = Hc; p.ldc = Hc;
        p.Arpc = BIG; p.Achunk = 0;
        gemm16_k<0><<<dim3(Hc / 128, Bn * Sc / 128, 1), 256>>>(p);
    }
}